// round 8
// baseline (speedup 1.0000x reference)
#include <cuda_runtime.h>
#include <cuda_bf16.h>
#include <math.h>
#include <stdint.h>

#define NB 4
#define LL 4096
#define SS 4096
#define HH 8
#define NHD 32
#define NTOK (NB*LL*HH)    // 131072

typedef __nv_bfloat16 bf16;

// ---------------- scratch ----------------
__device__ float g_kv[NHD*64*64];
__device__ float g_ksum[NHD*64];
__device__ float g_msg[NTOK*64];

// ---------------- k0 ----------------
__global__ void k0_zero() {
    int i = blockIdx.x * blockDim.x + threadIdx.x;
    if (i < NHD*64*64) g_kv[i] = 0.f;
    if (i < NHD*64)    g_ksum[i] = 0.f;
}

// ================= mma helpers (validated in R7 k3) =================
__device__ __forceinline__ void mma_bf16(float d[4], const uint32_t a[4],
                                         uint32_t b0, uint32_t b1) {
    asm volatile("mma.sync.aligned.m16n8k16.row.col.f32.bf16.bf16.f32 "
        "{%0,%1,%2,%3}, {%4,%5,%6,%7}, {%8,%9}, {%0,%1,%2,%3};"
        : "+f"(d[0]), "+f"(d[1]), "+f"(d[2]), "+f"(d[3])
        : "r"(a[0]), "r"(a[1]), "r"(a[2]), "r"(a[3]), "r"(b0), "r"(b1));
}

__device__ __forceinline__ void split2(float v0, float v1, uint32_t& hi, uint32_t& lo) {
    bf16 h0 = __float2bfloat16(v0);
    bf16 h1 = __float2bfloat16(v1);
    __nv_bfloat162 hh = __halves2bfloat162(h0, h1);
    hi = *(uint32_t*)&hh;
    __nv_bfloat162 ll = __halves2bfloat162(
        __float2bfloat16(v0 - __bfloat162float(h0)),
        __float2bfloat16(v1 - __bfloat162float(h1)));
    lo = *(uint32_t*)&ll;
}

// warp GEMM: M32 (2 mtiles), N = NT*8, K = NK*16, 3-term bf16 split
template<int NT, int NK>
__device__ __forceinline__ void warp_gemm(float acc[2][NT][4],
    const bf16* __restrict__ Ah, const bf16* __restrict__ Al, int sa, int mrow0,
    const bf16* __restrict__ Bh, const bf16* __restrict__ Bl, int sb, int ncol0,
    int lane)
{
    int r = lane >> 2, c2 = (lane & 3)*2;
    #pragma unroll
    for (int ks = 0; ks < NK; ks++) {
        uint32_t ah[2][4], al[2][4];
        #pragma unroll
        for (int mt = 0; mt < 2; mt++) {
            const bf16* pa = Ah + (mrow0 + mt*16 + r)*sa + ks*16 + c2;
            const bf16* pl = Al + (mrow0 + mt*16 + r)*sa + ks*16 + c2;
            ah[mt][0] = *(const uint32_t*)(pa);
            ah[mt][1] = *(const uint32_t*)(pa + 8*sa);
            ah[mt][2] = *(const uint32_t*)(pa + 8);
            ah[mt][3] = *(const uint32_t*)(pa + 8*sa + 8);
            al[mt][0] = *(const uint32_t*)(pl);
            al[mt][1] = *(const uint32_t*)(pl + 8*sa);
            al[mt][2] = *(const uint32_t*)(pl + 8);
            al[mt][3] = *(const uint32_t*)(pl + 8*sa + 8);
        }
        #pragma unroll
        for (int nt = 0; nt < NT; nt++) {
            const bf16* pbh = Bh + (ncol0 + nt*8 + r)*sb + ks*16 + c2;
            const bf16* pbl = Bl + (ncol0 + nt*8 + r)*sb + ks*16 + c2;
            uint32_t bh0 = *(const uint32_t*)(pbh);
            uint32_t bh1 = *(const uint32_t*)(pbh + 8);
            uint32_t bl0 = *(const uint32_t*)(pbl);
            uint32_t bl1 = *(const uint32_t*)(pbl + 8);
            #pragma unroll
            for (int mt = 0; mt < 2; mt++) {
                mma_bf16(acc[mt][nt], ah[mt], bh0, bh1);
                mma_bf16(acc[mt][nt], ah[mt], bl0, bl1);
                mma_bf16(acc[mt][nt], al[mt], bh0, bh1);
            }
        }
    }
}

__device__ __forceinline__ float elu1(float v) {
    return (v > 0.f) ? (v + 1.f) : expf(v);
}

// =================================================================
// k1: kT/vT projection (flipped GEMM) + kv outer product, all mma
// grid (SS/128, NHD), block 256 (8 warps), smem 140KB -> 1 CTA/SM
// =================================================================
#define SO1_WKH 0
#define SO1_WKL 9216
#define SO1_WVH 18432
#define SO1_WVL 27648
#define SO1_SRH 36864
#define SO1_SRL 55296
#define SO1_KTH 73728
#define SO1_KTL 91136
#define SO1_VTH 108544
#define SO1_VTL 125952
#define SMEM1M  143360

__global__ void __launch_bounds__(256, 1)
k1_mma(const float* __restrict__ src,
       const float* __restrict__ wk,
       const float* __restrict__ wv) {
    extern __shared__ char smem[];
    bf16* WKH = (bf16*)(smem + SO1_WKH);
    bf16* WKL = (bf16*)(smem + SO1_WKL);
    bf16* WVH = (bf16*)(smem + SO1_WVH);
    bf16* WVL = (bf16*)(smem + SO1_WVL);
    bf16* SRH = (bf16*)(smem + SO1_SRH);   // src [s=128][d=64] stride 72
    bf16* SRL = (bf16*)(smem + SO1_SRL);
    bf16* KTH = (bf16*)(smem + SO1_KTH);   // kT [dk=64][s=128] stride 136
    bf16* KTL = (bf16*)(smem + SO1_KTL);
    bf16* VTH = (bf16*)(smem + SO1_VTH);
    bf16* VTL = (bf16*)(smem + SO1_VTL);

    int tid = threadIdx.x, lane = tid & 31, w = tid >> 5;
    int r = lane >> 2, c2 = (lane & 3)*2;
    int nh = blockIdx.y, n = nh >> 3, h = nh & 7;
    int s0 = blockIdx.x * 128;

    // weights -> bf16 hi/lo ([e][d] natural = B/A layouts as needed)
    for (int i = tid; i < 4096; i += 256) {
        int e = i >> 6, d = i & 63;
        float vk = wk[i], vv = wv[i];
        bf16 hk = __float2bfloat16(vk);
        WKH[e*72 + d] = hk;
        WKL[e*72 + d] = __float2bfloat16(vk - __bfloat162float(hk));
        bf16 hv = __float2bfloat16(vv);
        WVH[e*72 + d] = hv;
        WVL[e*72 + d] = __float2bfloat16(vv - __bfloat162float(hv));
    }
    // src chunk -> bf16 hi/lo
    for (int i = tid; i < 4096; i += 256) {
        int t = i >> 5, j = (i & 31)*2;
        float2 sv = *(const float2*)(src + ((size_t)(n*SS + s0 + t)*HH + h)*64 + j);
        uint32_t hi, lo;
        split2(sv.x, sv.y, hi, lo);
        *(uint32_t*)(SRH + t*72 + j) = hi;
        *(uint32_t*)(SRL + t*72 + j) = lo;
    }
    __syncthreads();

    // ---- proj (flipped): kT[e][s] = wk @ src^T  (M=64, N=128, K=64) ----
    int wM = w & 1, wN = w >> 1;   // 2 x 4
    {
        float acc[2][4][4];
        #pragma unroll
        for (int i = 0; i < 2; i++)
            #pragma unroll
            for (int j = 0; j < 4; j++)
                #pragma unroll
                for (int q = 0; q < 4; q++) acc[i][j][q] = 0.f;
        warp_gemm<4,4>(acc, WKH, WKL, 72, wM*32, SRH, SRL, 72, wN*32, lane);
        #pragma unroll
        for (int mt = 0; mt < 2; mt++)
            #pragma unroll
            for (int nt = 0; nt < 4; nt++) {
                int rr = wM*32 + mt*16 + r;
                int cc = wN*32 + nt*8 + c2;
                uint32_t hi, lo;
                split2(elu1(acc[mt][nt][0]), elu1(acc[mt][nt][1]), hi, lo);
                *(uint32_t*)(KTH + rr*136 + cc) = hi;
                *(uint32_t*)(KTL + rr*136 + cc) = lo;
                split2(elu1(acc[mt][nt][2]), elu1(acc[mt][nt][3]), hi, lo);
                *(uint32_t*)(KTH + (rr+8)*136 + cc) = hi;
                *(uint32_t*)(KTL + (rr+8)*136 + cc) = lo;
            }
    }
    // ---- proj V: vT[e][s] ----
    {
        float acc[2][4][4];
        #pragma unroll
        for (int i = 0; i < 2; i++)
            #pragma unroll
            for (int j = 0; j < 4; j++)
                #pragma unroll
                for (int q = 0; q < 4; q++) acc[i][j][q] = 0.f;
        warp_gemm<4,4>(acc, WVH, WVL, 72, wM*32, SRH, SRL, 72, wN*32, lane);
        #pragma unroll
        for (int mt = 0; mt < 2; mt++)
            #pragma unroll
            for (int nt = 0; nt < 4; nt++) {
                int rr = wM*32 + mt*16 + r;
                int cc = wN*32 + nt*8 + c2;
                uint32_t hi, lo;
                split2(acc[mt][nt][0], acc[mt][nt][1], hi, lo);
                *(uint32_t*)(VTH + rr*136 + cc) = hi;
                *(uint32_t*)(VTL + rr*136 + cc) = lo;
                split2(acc[mt][nt][2], acc[mt][nt][3], hi, lo);
                *(uint32_t*)(VTH + (rr+8)*136 + cc) = hi;
                *(uint32_t*)(VTL + (rr+8)*136 + cc) = lo;
            }
    }
    __syncthreads();

    // ---- outer: kv[dk][dv] += kT @ vT^T  (M=64, N=64, K=128 split x2) ----
    {
        int wK = w >> 2, wM2 = (w >> 1) & 1, wN2 = w & 1;
        float acc[2][4][4];
        #pragma unroll
        for (int i = 0; i < 2; i++)
            #pragma unroll
            for (int j = 0; j < 4; j++)
                #pragma unroll
                for (int q = 0; q < 4; q++) acc[i][j][q] = 0.f;
        warp_gemm<4,4>(acc, KTH + wK*64, KTL + wK*64, 136, wM2*32,
                            VTH + wK*64, VTL + wK*64, 136, wN2*32, lane);
        float* kvg = g_kv + nh*4096;
        #pragma unroll
        for (int mt = 0; mt < 2; mt++)
            #pragma unroll
            for (int nt = 0; nt < 4; nt++) {
                int rr = wM2*32 + mt*16 + r;
                int cc = wN2*32 + nt*8 + c2;
                atomicAdd(kvg + rr*64 + cc,       acc[mt][nt][0]);
                atomicAdd(kvg + rr*64 + cc + 1,   acc[mt][nt][1]);
                atomicAdd(kvg + (rr+8)*64 + cc,   acc[mt][nt][2]);
                atomicAdd(kvg + (rr+8)*64 + cc+1, acc[mt][nt][3]);
            }
    }

    // ---- ksum from kT rows (contiguous) ----
    if (tid < 64) {
        const __nv_bfloat162* ph = (const __nv_bfloat162*)(KTH + tid*136);
        const __nv_bfloat162* pl = (const __nv_bfloat162*)(KTL + tid*136);
        float s = 0.f;
        #pragma unroll 8
        for (int i = 0; i < 64; i++) {
            float2 a = __bfloat1622float2(ph[i]);
            float2 b = __bfloat1622float2(pl[i]);
            s += a.x + a.y + b.x + b.y;
        }
        atomicAdd(g_ksum + nh*64 + tid, s);
    }
}

// =================================================================
// k2: q projection + attention apply, all mma
// grid (LL/128, NHD), block 256, smem ~74KB -> 2 CTA/SM
// =================================================================
#define SO2_WQH 0
#define SO2_WQL 9216
#define SO2_KVH 18432
#define SO2_KVL 27648
#define SO2_XH  36864
#define SO2_XL  55296
#define SO2_KS  73728
#define SO2_ZB  73984
#define SMEM2M  74496

__global__ void __launch_bounds__(256, 2)
k2_mma(const float* __restrict__ x,
       const float* __restrict__ wq) {
    extern __shared__ char smem[];
    bf16* WQH = (bf16*)(smem + SO2_WQH);
    bf16* WQL = (bf16*)(smem + SO2_WQL);
    bf16* KVH = (bf16*)(smem + SO2_KVH);   // kvT [dv=64][dk=64] stride 72
    bf16* KVL = (bf16*)(smem + SO2_KVL);
    bf16* XH  = (bf16*)(smem + SO2_XH);    // x [l=128][d=64] stride 72; later q
    bf16* XL  = (bf16*)(smem + SO2_XL);
    float* ksb = (float*)(smem + SO2_KS);
    float* zb  = (float*)(smem + SO2_ZB);

    int tid = threadIdx.x, lane = tid & 31, w = tid >> 5;
    int r = lane >> 2, c2 = (lane & 3)*2;
    int wM = w & 3, wN = w >> 2;    // 4 x 2
    int nh = blockIdx.y, n = nh >> 3, h = nh & 7;
    int l0 = blockIdx.x * 128;

    for (int i = tid; i < 4096; i += 256) {
        int e = i >> 6, d = i & 63;
        float v = wq[i];
        bf16 hh = __float2bfloat16(v);
        WQH[e*72 + d] = hh;
        WQL[e*72 + d] = __float2bfloat16(v - __bfloat162float(hh));
        // kv transposed: [dk][dv] -> kvT[dv][dk]
        int dk = i >> 6, dv = i & 63;
        float kvv = g_kv[nh*4096 + i];
        bf16 kh = __float2bfloat16(kvv);
        KVH[dv*72 + dk] = kh;
        KVL[dv*72 + dk] = __float2bfloat16(kvv - __bfloat162float(kh));
    }
    for (int i = tid; i < 4096; i += 256) {
        int t = i >> 5, j = (i & 31)*2;
        float2 xv = *(const float2*)(x + ((size_t)(n*LL + l0 + t)*HH + h)*64 + j);
        uint32_t hi, lo;
        split2(xv.x, xv.y, hi, lo);
        *(uint32_t*)(XH + t*72 + j) = hi;
        *(uint32_t*)(XL + t*72 + j) = lo;
    }
    if (tid < 64) ksb[tid] = g_ksum[nh*64 + tid];
    __syncthreads();

    // ---- proj: q[l][e] = x @ wq^T (M=128, N=64, K=64) ----
    float accQ[2][4][4];
    #pragma unroll
    for (int i = 0; i < 2; i++)
        #pragma unroll
        for (int j = 0; j < 4; j++)
            #pragma unroll
            for (int q = 0; q < 4; q++) accQ[i][j][q] = 0.f;
    warp_gemm<4,4>(accQ, XH, XL, 72, wM*32, WQH, WQL, 72, wN*32, lane);
    // elu+1 in place
    #pragma unroll
    for (int i = 0; i < 2; i++)
        #pragma unroll
        for (int j = 0; j < 4; j++)
            #pragma unroll
            for (int q = 0; q < 4; q++) accQ[i][j][q] = elu1(accQ[i][j][q]);
    __syncthreads();   // x reads done; safe to overwrite with q

    #pragma unroll
    for (int mt = 0; mt < 2; mt++)
        #pragma unroll
        for (int nt = 0; nt < 4; nt++) {
            int rr = wM*32 + mt*16 + r;
            int cc = wN*32 + nt*8 + c2;
            uint32_t hi, lo;
            split2(accQ[mt][nt][0], accQ[mt][nt][1], hi, lo);
            *(uint32_t*)(XH + rr*72 + cc) = hi;
            *(uint32_t*)(XL + rr*72 + cc) = lo;
            split2(accQ[mt][nt][2], accQ[mt][nt][3], hi, lo);
            *(uint32_t*)(XH + (rr+8)*72 + cc) = hi;
            *(uint32_t*)(XL + (rr+8)*72 + cc) = lo;
        }
    __syncthreads();

    // ---- z = 1/(q . ksum + eps) per row ----
    if (tid < 128) {
        const __nv_bfloat162* ph = (const __nv_bfloat162*)(XH + tid*72);
        const __nv_bfloat162* pl = (const __nv_bfloat162*)(XL + tid*72);
        float s = 0.f;
        #pragma unroll 8
        for (int i = 0; i < 32; i++) {
            float2 a = __bfloat1622float2(ph[i]);
            float2 b = __bfloat1622float2(pl[i]);
            s += (a.x + b.x)*ksb[2*i] + (a.y + b.y)*ksb[2*i + 1];
        }
        zb[tid] = 1.f / (s + 1e-6f);
    }
    __syncthreads();

    // ---- apply: msg[l][dv] = q @ kv (M=128, N=64, K=64) ----
    float accM[2][4][4];
    #pragma unroll
    for (int i = 0; i < 2; i++)
        #pragma unroll
        for (int j = 0; j < 4; j++)
            #pragma unroll
            for (int q = 0; q < 4; q++) accM[i][j][q] = 0.f;
    warp_gemm<4,4>(accM, XH, XL, 72, wM*32, KVH, KVL, 72, wN*32, lane);
    #pragma unroll
    for (int mt = 0; mt < 2; mt++)
        #pragma unroll
        for (int nt = 0; nt < 4; nt++) {
            int rr = wM*32 + mt*16 + r;
            int cc = wN*32 + nt*8 + c2;
            float z0 = zb[rr], z1 = zb[rr + 8];
            size_t row0 = ((size_t)(n*LL + l0 + rr)*HH + h)*64;
            size_t row1 = ((size_t)(n*LL + l0 + rr + 8)*HH + h)*64;
            float2 o0 = {accM[mt][nt][0]*z0, accM[mt][nt][1]*z0};
            float2 o1 = {accM[mt][nt][2]*z1, accM[mt][nt][3]*z1};
            *(float2*)(g_msg + row0 + cc) = o0;
            *(float2*)(g_msg + row1 + cc) = o1;
        }
}

// =================================================================
// k3: mma.sync bf16x3 merge+LN1+FFN+LN2+residual (proven @ R7)
// =================================================================
__device__ __forceinline__ void quad_reduce2(float& s, float& q) {
    s += __shfl_xor_sync(0xffffffffu, s, 1);
    q += __shfl_xor_sync(0xffffffffu, q, 1);
    s += __shfl_xor_sync(0xffffffffu, s, 2);
    q += __shfl_xor_sync(0xffffffffu, q, 2);
}

#define SO_W1H 0
#define SO_W1L 34816
#define SO_W2H 69632
#define SO_W2L 87040
#define SO_WMH 104448
#define SO_WML 113664
#define SO_HH  122880
#define SO_HL  140288
#define SO_H1H 157696
#define SO_H1L 175104
#define SO_XB  192512
#define SO_GB  209408
#define SO_PS  210432
#define SO_PQ  211456
#define SO_MEAN 212480
#define SO_INV 212736
#define SMEM3M 212992

__global__ void __launch_bounds__(256, 1)
k3_mma(const float* __restrict__ x,
       const float* __restrict__ wm,
       const float* __restrict__ w1,
       const float* __restrict__ w2,
       const float* __restrict__ g1, const float* __restrict__ b1,
       const float* __restrict__ g2, const float* __restrict__ b2,
       float* __restrict__ out) {
    extern __shared__ char smem[];
    bf16* W1H = (bf16*)(smem + SO_W1H);
    bf16* W1L = (bf16*)(smem + SO_W1L);
    bf16* W2H = (bf16*)(smem + SO_W2H);
    bf16* W2L = (bf16*)(smem + SO_W2L);
    bf16* WMH = (bf16*)(smem + SO_WMH);
    bf16* WML = (bf16*)(smem + SO_WML);
    bf16* Hh  = (bf16*)(smem + SO_HH);
    bf16* Hl  = (bf16*)(smem + SO_HL);
    bf16* H1h = (bf16*)(smem + SO_H1H);
    bf16* H1l = (bf16*)(smem + SO_H1L);
    float* xb    = (float*)(smem + SO_XB);
    float* gbuf  = (float*)(smem + SO_GB);
    float* ps    = (float*)(smem + SO_PS);
    float* pq    = (float*)(smem + SO_PQ);
    float* means = (float*)(smem + SO_MEAN);
    float* invs  = (float*)(smem + SO_INV);

    int tid = threadIdx.x, lane = tid & 31, w = tid >> 5;
    int wM = w & 1, wN = w >> 1;
    int r = lane >> 2, c2 = (lane & 3)*2;

    for (int i = tid; i < 16384; i += 256) {
        int nn = i >> 7, kk = i & 127;
        float v = w1[i];
        bf16 h = __float2bfloat16(v);
        W1H[nn*136 + kk] = h;
        W1L[nn*136 + kk] = __float2bfloat16(v - __bfloat162float(h));
    }
    for (int i = tid; i < 8192; i += 256) {
        int nn = i >> 7, kk = i & 127;
        float v = w2[i];
        bf16 h = __float2bfloat16(v);
        W2H[nn*136 + kk] = h;
        W2L[nn*136 + kk] = __float2bfloat16(v - __bfloat162float(h));
    }
    for (int i = tid; i < 4096; i += 256) {
        int nn = i >> 6, kk = i & 63;
        float v = wm[i];
        bf16 h = __float2bfloat16(v);
        WMH[nn*72 + kk] = h;
        WML[nn*72 + kk] = __float2bfloat16(v - __bfloat162float(h));
    }
    if (tid < 64) {
        gbuf[tid]       = g1[tid];
        gbuf[64 + tid]  = b1[tid];
        gbuf[128 + tid] = g2[tid];
        gbuf[192 + tid] = b2[tid];
    }
    __syncthreads();

    for (int tile = blockIdx.x; tile < NTOK/64; tile += gridDim.x) {
        int tok0 = tile * 64;

        for (int i = tid; i < 2048; i += 256) {
            int t = i >> 5, j = (i & 31)*2;
            float2 mv = *(const float2*)(g_msg + (size_t)(tok0 + t)*64 + j);
            uint32_t hi, lo;
            split2(mv.x, mv.y, hi, lo);
            *(uint32_t*)(H1h + t*136 + j) = hi;
            *(uint32_t*)(H1l + t*136 + j) = lo;
            float2 xv = *(const float2*)(x + (size_t)(tok0 + t)*64 + j);
            split2(xv.x, xv.y, hi, lo);
            *(uint32_t*)(Hh + t*136 + j) = hi;
            *(uint32_t*)(Hl + t*136 + j) = lo;
            *(float2*)(xb + t*66 + j) = xv;
        }
        __syncthreads();

        float accA[2][2][4];
        #pragma unroll
        for (int i = 0; i < 2; i++)
            #pragma unroll
            for (int j = 0; j < 2; j++)
                #pragma unroll
                for (int q = 0; q < 4; q++) accA[i][j][q] = 0.f;
        warp_gemm<2,4>(accA, H1h, H1l, 136, wM*32, WMH, WML, 72, wN*16, lane);

        #pragma unroll
        for (int mt = 0; mt < 2; mt++) {
            float s0 = 0.f, q0 = 0.f, s1 = 0.f, q1 = 0.f;
            #pragma unroll
            for (int nt = 0; nt < 2; nt++) {
                float a0 = accA[mt][nt][0], a1 = accA[mt][nt][1];
                float a2 = accA[mt][nt][2], a3 = accA[mt][nt][3];
                s0 += a0 + a1; q0 += a0*a0 + a1*a1;
                s1 += a2 + a3; q1 += a2*a2 + a3*a3;
            }
            quad_reduce2(s0, q0);
            quad_reduce2(s1, q1);
            if ((lane & 3) == 0) {
                int rr = wM*32 + mt*16 + r;
                ps[rr*4 + wN] = s0;      pq[rr*4 + wN] = q0;
                ps[(rr+8)*4 + wN] = s1;  pq[(rr+8)*4 + wN] = q1;
            }
        }
        __syncthreads();
        if (tid < 64) {
            float s = ps[tid*4] + ps[tid*4+1] + ps[tid*4+2] + ps[tid*4+3];
            float q = pq[tid*4] + pq[tid*4+1] + pq[tid*4+2] + pq[tid*4+3];
            float mean = s * (1.f/64.f);
            float var  = q * (1.f/64.f) - mean*mean;
            means[tid] = mean;
            invs[tid]  = rsqrtf(var + 1e-5f);
        }
        __syncthreads();

        #pragma unroll
        for (int mt = 0; mt < 2; mt++)
            #pragma unroll
            for (int nt = 0; nt < 2; nt++) {
                int rr = wM*32 + mt*16 + r;
                int cc = wN*16 + nt*8 + c2;
                float m0 = means[rr], i0 = invs[rr];
                float y0 = (accA[mt][nt][0] - m0)*i0*gbuf[cc]   + gbuf[64+cc];
                float y1 = (accA[mt][nt][1] - m0)*i0*gbuf[cc+1] + gbuf[64+cc+1];
                uint32_t hi, lo;
                split2(y0, y1, hi, lo);
                *(uint32_t*)(Hh + rr*136 + 64 + cc) = hi;
                *(uint32_t*)(Hl + rr*136 + 64 + cc) = lo;
                float m1 = means[rr+8], i1 = invs[rr+8];
                float y2 = (accA[mt][nt][2] - m1)*i1*gbuf[cc]   + gbuf[64+cc];
                float y3 = (accA[mt][nt][3] - m1)*i1*gbuf[cc+1] + gbuf[64+cc+1];
                split2(y2, y3, hi, lo);
                *(uint32_t*)(Hh + (rr+8)*136 + 64 + cc) = hi;
                *(uint32_t*)(Hl + (rr+8)*136 + 64 + cc) = lo;
            }
        __syncthreads();

        float accB[2][4][4];
        #pragma unroll
        for (int i = 0; i < 2; i++)
            #pragma unroll
            for (int j = 0; j < 4; j++)
                #pragma unroll
                for (int q = 0; q < 4; q++) accB[i][j][q] = 0.f;
        warp_gemm<4,8>(accB, Hh, Hl, 136, wM*32, W1H, W1L, 136, wN*32, lane);

        #pragma unroll
        for (int mt = 0; mt < 2; mt++)
            #pragma unroll
            for (int nt = 0; nt < 4; nt++) {
                int rr = wM*32 + mt*16 + r;
                int cc = wN*32 + nt*8 + c2;
                uint32_t hi, lo;
                split2(fmaxf(accB[mt][nt][0], 0.f), fmaxf(accB[mt][nt][1], 0.f), hi, lo);
                *(uint32_t*)(H1h + rr*136 + cc) = hi;
                *(uint32_t*)(H1l + rr*136 + cc) = lo;
                split2(fmaxf(accB[mt][nt][2], 0.f), fmaxf(accB[mt][nt][3], 0.f), hi, lo);
                *(uint32_t*)(H1h + (rr+8)*136 + cc) = hi;
                *(uint32_t*)(H1l + (rr+8)*136 + cc) = lo;
            }
        __syncthreads();

        float accC[2][2][4];
        #pragma unroll
        for (int i = 0; i < 2; i++)
            #pragma unroll
            for (int j = 0; j < 2; j++)
                #pragma unroll
                for (int q = 0; q < 4; q++) accC[i][j][q] = 0.f;
        warp_gemm<2,8>(accC, H1h, H1l, 136, wM*32, W2H, W2L, 136, wN*16, lane);

        #pragma unroll
        for (int mt = 0; mt < 2; mt++) {
            float s0 = 0.f, q0 = 0.f, s1 = 0.f, q1 = 0.f;
            #pragma unroll
            for (int nt = 0; nt < 2; nt++) {
                float a0 = accC[mt][nt][0], a1 = accC[mt][nt][1];
                float a2 = accC[mt][nt][2], a3 = accC[mt][nt][3];
                s0 += a0 + a1; q0 += a0*a0 + a1*a1;
                s1 += a2 + a3; q1 += a2*a2 + a3*a3;
            }
            quad_reduce2(s0, q0);
            quad_reduce2(s1, q1);
            if ((lane & 3) == 0) {
                int rr = wM*32 + mt*16 + r;
                ps[rr*4 + wN] = s0;      pq[rr*4 + wN] = q0;
                ps[(rr+8)*4 + wN] = s1;  pq[(rr+8)*4 + wN] = q1;
            }
        }
        __syncthreads();
        if (tid < 64) {
            float s = ps[tid*4] + ps[tid*4+1] + ps[tid*4+2] + ps[tid*4+3];
            float q = pq[tid*4] + pq[tid*4+1] + pq[tid*4+2] + pq[tid*4+3];
            float mean = s * (1.f/64.f);
            float var  = q * (1.f/64.f) - mean*mean;
            means[tid] = mean;
            invs[tid]  = rsqrtf(var + 1e-5f);
        }
        __syncthreads();

        #pragma unroll
        for (int mt = 0; mt < 2; mt++)
            #pragma unroll
            for (int nt = 0; nt < 2; nt++) {
                int rr = wM*32 + mt*16 + r;
                int cc = wN*16 + nt*8 + c2;
                float m0 = means[rr], i0 = invs[rr];
                float2 xv = *(const float2*)(xb + rr*66 + cc);
                float2 o0;
                o0.x = xv.x + (accC[mt][nt][0] - m0)*i0*gbuf[128+cc]   + gbuf[192+cc];
                o0.y = xv.y + (accC[mt][nt][1] - m0)*i0*gbuf[128+cc+1] + gbuf[192+cc+1];
                *(float2*)(out + (size_t)(tok0 + rr)*64 + cc) = o0;
                float m1 = means[rr+8], i1 = invs[rr+8];
                float2 xw = *(const float2*)(xb + (rr+8)*66 + cc);
                float2 o1;
                o1.x = xw.x + (accC[mt][nt][2] - m1)*i1*gbuf[128+cc]   + gbuf[192+cc];
                o1.y = xw.y + (accC[mt][nt][3] - m1)*i1*gbuf[128+cc+1] + gbuf[192+cc+1];
                *(float2*)(out + (size_t)(tok0 + rr + 8)*64 + cc) = o1;
            }
        __syncthreads();
    }
}

// ---------------- launch ----------------
extern "C" void kernel_launch(void* const* d_in, const int* in_sizes, int n_in,
                              void* d_out, int out_size) {
    const float* x   = (const float*)d_in[0];
    const float* src = (const float*)d_in[1];
    const float* wq  = (const float*)d_in[2];
    const float* wk  = (const float*)d_in[3];
    const float* wv  = (const float*)d_in[4];
    const float* wm  = (const float*)d_in[5];
    const float* w1  = (const float*)d_in[6];
    const float* w2  = (const float*)d_in[7];
    const float* g1  = (const float*)d_in[8];
    const float* b1  = (const float*)d_in[9];
    const float* g2  = (const float*)d_in[10];
    const float* b2  = (const float*)d_in[11];
    float* out = (float*)d_out;

    cudaFuncSetAttribute(k1_mma, cudaFuncAttributeMaxDynamicSharedMemorySize, SMEM1M);
    cudaFuncSetAttribute(k2_mma, cudaFuncAttributeMaxDynamicSharedMemorySize, SMEM2M);
    cudaFuncSetAttribute(k3_mma, cudaFuncAttributeMaxDynamicSharedMemorySize, SMEM3M);

    k0_zero<<<512, 256>>>();
    k1_mma<<<dim3(SS/128, NHD), 256, SMEM1M>>>(src, wk, wv);
    k2_mma<<<dim3(LL/128, NHD), 256, SMEM2M>>>(x, wq);
    k3_mma<<<148, 256, SMEM3M>>>(x, wm, w1, w2, g1, b1, g2, b2, out);
}

// round 11
// speedup vs baseline: 1.0687x; 1.0687x over previous
#include <cuda_runtime.h>
#include <cuda_bf16.h>
#include <math.h>
#include <stdint.h>

#define NB 4
#define LL 4096
#define SS 4096
#define HH 8
#define NHD 32
#define NTOK (NB*LL*HH)    // 131072

typedef __nv_bfloat16 bf16;

// ---------------- scratch ----------------
__device__ float g_kv[NHD*64*64];
__device__ float g_ksum[NHD*64];
__device__ float g_msg[NTOK*64];

// ---------------- k0 ----------------
__global__ void k0_zero() {
    int i = blockIdx.x * blockDim.x + threadIdx.x;
    if (i < NHD*64*64) g_kv[i] = 0.f;
    if (i < NHD*64)    g_ksum[i] = 0.f;
}

// ================= mma helpers =================
__device__ __forceinline__ void mma_bf16(float d[4], const uint32_t a[4],
                                         uint32_t b0, uint32_t b1) {
    asm volatile("mma.sync.aligned.m16n8k16.row.col.f32.bf16.bf16.f32 "
        "{%0,%1,%2,%3}, {%4,%5,%6,%7}, {%8,%9}, {%0,%1,%2,%3};"
        : "+f"(d[0]), "+f"(d[1]), "+f"(d[2]), "+f"(d[3])
        : "r"(a[0]), "r"(a[1]), "r"(a[2]), "r"(a[3]), "r"(b0), "r"(b1));
}

__device__ __forceinline__ void split2(float v0, float v1, uint32_t& hi, uint32_t& lo) {
    bf16 h0 = __float2bfloat16(v0);
    bf16 h1 = __float2bfloat16(v1);
    __nv_bfloat162 hh = __halves2bfloat162(h0, h1);
    hi = *(uint32_t*)&hh;
    __nv_bfloat162 ll = __halves2bfloat162(
        __float2bfloat16(v0 - __bfloat162float(h0)),
        __float2bfloat16(v1 - __bfloat162float(h1)));
    lo = *(uint32_t*)&ll;
}

// warp GEMM: M32 (2 mtiles), N = NT*8, K = NK*16, 3-term bf16 split
template<int NT, int NK>
__device__ __forceinline__ void warp_gemm(float acc[2][NT][4],
    const bf16* __restrict__ Ah, const bf16* __restrict__ Al, int sa, int mrow0,
    const bf16* __restrict__ Bh, const bf16* __restrict__ Bl, int sb, int ncol0,
    int lane)
{
    int r = lane >> 2, c2 = (lane & 3)*2;
    #pragma unroll
    for (int ks = 0; ks < NK; ks++) {
        uint32_t ah[2][4], al[2][4];
        #pragma unroll
        for (int mt = 0; mt < 2; mt++) {
            const bf16* pa = Ah + (mrow0 + mt*16 + r)*sa + ks*16 + c2;
            const bf16* pl = Al + (mrow0 + mt*16 + r)*sa + ks*16 + c2;
            ah[mt][0] = *(const uint32_t*)(pa);
            ah[mt][1] = *(const uint32_t*)(pa + 8*sa);
            ah[mt][2] = *(const uint32_t*)(pa + 8);
            ah[mt][3] = *(const uint32_t*)(pa + 8*sa + 8);
            al[mt][0] = *(const uint32_t*)(pl);
            al[mt][1] = *(const uint32_t*)(pl + 8*sa);
            al[mt][2] = *(const uint32_t*)(pl + 8);
            al[mt][3] = *(const uint32_t*)(pl + 8*sa + 8);
        }
        #pragma unroll
        for (int nt = 0; nt < NT; nt++) {
            const bf16* pbh = Bh + (ncol0 + nt*8 + r)*sb + ks*16 + c2;
            const bf16* pbl = Bl + (ncol0 + nt*8 + r)*sb + ks*16 + c2;
            uint32_t bh0 = *(const uint32_t*)(pbh);
            uint32_t bh1 = *(const uint32_t*)(pbh + 8);
            uint32_t bl0 = *(const uint32_t*)(pbl);
            uint32_t bl1 = *(const uint32_t*)(pbl + 8);
            #pragma unroll
            for (int mt = 0; mt < 2; mt++) {
                mma_bf16(acc[mt][nt], ah[mt], bh0, bh1);
                mma_bf16(acc[mt][nt], ah[mt], bl0, bl1);
                mma_bf16(acc[mt][nt], al[mt], bh0, bh1);
            }
        }
    }
}

__device__ __forceinline__ float elu1(float v) {
    return (v > 0.f) ? (v + 1.f) : expf(v);
}

// =================================================================
// k1: kT/vT projection (flipped GEMM) + kv outer product
// grid (SS/128, NHD), block 256, smem 108.5KB -> 2 CTA/SM
// VT aliases the src buffer (V-proj acc held in regs across sync)
// =================================================================
#define SO1_WKH 0
#define SO1_WKL 9216
#define SO1_WVH 18432
#define SO1_WVL 27648
#define SO1_SRH 36864
#define SO1_SRL 55296
#define SO1_KTH 73728
#define SO1_KTL 91136
#define SO1_VTH 36864          // alias over SRH
#define SO1_VTL 55296          // alias over SRL
#define SMEM1M  108544

__global__ void __launch_bounds__(256, 2)
k1_mma(const float* __restrict__ src,
       const float* __restrict__ wk,
       const float* __restrict__ wv) {
    extern __shared__ char smem[];
    bf16* WKH = (bf16*)(smem + SO1_WKH);
    bf16* WKL = (bf16*)(smem + SO1_WKL);
    bf16* WVH = (bf16*)(smem + SO1_WVH);
    bf16* WVL = (bf16*)(smem + SO1_WVL);
    bf16* SRH = (bf16*)(smem + SO1_SRH);   // src [s=128][d=64] stride 72
    bf16* SRL = (bf16*)(smem + SO1_SRL);
    bf16* KTH = (bf16*)(smem + SO1_KTH);   // kT [dk=64][s=128] stride 136
    bf16* KTL = (bf16*)(smem + SO1_KTL);
    bf16* VTH = (bf16*)(smem + SO1_VTH);   // vT aliases src
    bf16* VTL = (bf16*)(smem + SO1_VTL);

    int tid = threadIdx.x, lane = tid & 31, w = tid >> 5;
    int r = lane >> 2, c2 = (lane & 3)*2;
    int nh = blockIdx.y, n = nh >> 3, h = nh & 7;
    int s0 = blockIdx.x * 128;

    for (int i = tid; i < 4096; i += 256) {
        int e = i >> 6, d = i & 63;
        float vk = wk[i], vv = wv[i];
        bf16 hk = __float2bfloat16(vk);
        WKH[e*72 + d] = hk;
        WKL[e*72 + d] = __float2bfloat16(vk - __bfloat162float(hk));
        bf16 hv = __float2bfloat16(vv);
        WVH[e*72 + d] = hv;
        WVL[e*72 + d] = __float2bfloat16(vv - __bfloat162float(hv));
    }
    for (int i = tid; i < 4096; i += 256) {
        int t = i >> 5, j = (i & 31)*2;
        float2 sv = *(const float2*)(src + ((size_t)(n*SS + s0 + t)*HH + h)*64 + j);
        uint32_t hi, lo;
        split2(sv.x, sv.y, hi, lo);
        *(uint32_t*)(SRH + t*72 + j) = hi;
        *(uint32_t*)(SRL + t*72 + j) = lo;
    }
    __syncthreads();

    int wM = w & 1, wN = w >> 1;   // 2 x 4

    // ---- proj K (flipped): kT[e][s] = wk @ src^T  (M=64, N=128, K=64) ----
    float accK[2][4][4];
    #pragma unroll
    for (int i = 0; i < 2; i++)
        #pragma unroll
        for (int j = 0; j < 4; j++)
            #pragma unroll
            for (int q = 0; q < 4; q++) accK[i][j][q] = 0.f;
    warp_gemm<4,4>(accK, WKH, WKL, 72, wM*32, SRH, SRL, 72, wN*32, lane);

    // ---- proj V (acc stays in regs; SR still live) ----
    float accV[2][4][4];
    #pragma unroll
    for (int i = 0; i < 2; i++)
        #pragma unroll
        for (int j = 0; j < 4; j++)
            #pragma unroll
            for (int q = 0; q < 4; q++) accV[i][j][q] = 0.f;
    warp_gemm<4,4>(accV, WVH, WVL, 72, wM*32, SRH, SRL, 72, wN*32, lane);

    // write KT (separate region, safe before sync)
    #pragma unroll
    for (int mt = 0; mt < 2; mt++)
        #pragma unroll
        for (int nt = 0; nt < 4; nt++) {
            int rr = wM*32 + mt*16 + r;
            int cc = wN*32 + nt*8 + c2;
            uint32_t hi, lo;
            split2(elu1(accK[mt][nt][0]), elu1(accK[mt][nt][1]), hi, lo);
            *(uint32_t*)(KTH + rr*136 + cc) = hi;
            *(uint32_t*)(KTL + rr*136 + cc) = lo;
            split2(elu1(accK[mt][nt][2]), elu1(accK[mt][nt][3]), hi, lo);
            *(uint32_t*)(KTH + (rr+8)*136 + cc) = hi;
            *(uint32_t*)(KTL + (rr+8)*136 + cc) = lo;
        }
    __syncthreads();   // all SR reads complete

    // write VT over the dead src buffer
    #pragma unroll
    for (int mt = 0; mt < 2; mt++)
        #pragma unroll
        for (int nt = 0; nt < 4; nt++) {
            int rr = wM*32 + mt*16 + r;
            int cc = wN*32 + nt*8 + c2;
            uint32_t hi, lo;
            split2(accV[mt][nt][0], accV[mt][nt][1], hi, lo);
            *(uint32_t*)(VTH + rr*136 + cc) = hi;
            *(uint32_t*)(VTL + rr*136 + cc) = lo;
            split2(accV[mt][nt][2], accV[mt][nt][3], hi, lo);
            *(uint32_t*)(VTH + (rr+8)*136 + cc) = hi;
            *(uint32_t*)(VTL + (rr+8)*136 + cc) = lo;
        }
    __syncthreads();

    // ---- outer: kv[dk][dv] += kT @ vT^T  (M=64, N=64, K=128 split x2) ----
    {
        int wK = w >> 2, wM2 = (w >> 1) & 1, wN2 = w & 1;
        float acc[2][4][4];
        #pragma unroll
        for (int i = 0; i < 2; i++)
            #pragma unroll
            for (int j = 0; j < 4; j++)
                #pragma unroll
                for (int q = 0; q < 4; q++) acc[i][j][q] = 0.f;
        warp_gemm<4,4>(acc, KTH + wK*64, KTL + wK*64, 136, wM2*32,
                            VTH + wK*64, VTL + wK*64, 136, wN2*32, lane);
        float* kvg = g_kv + nh*4096;
        #pragma unroll
        for (int mt = 0; mt < 2; mt++)
            #pragma unroll
            for (int nt = 0; nt < 4; nt++) {
                int rr = wM2*32 + mt*16 + r;
                int cc = wN2*32 + nt*8 + c2;
                atomicAdd(kvg + rr*64 + cc,       acc[mt][nt][0]);
                atomicAdd(kvg + rr*64 + cc + 1,   acc[mt][nt][1]);
                atomicAdd(kvg + (rr+8)*64 + cc,   acc[mt][nt][2]);
                atomicAdd(kvg + (rr+8)*64 + cc+1, acc[mt][nt][3]);
            }
    }

    // ---- ksum, parallel: 4 threads per dk row ----
    {
        int row = tid >> 2, q = tid & 3;
        const __nv_bfloat162* ph = (const __nv_bfloat162*)(KTH + row*136) + q*16;
        const __nv_bfloat162* pl = (const __nv_bfloat162*)(KTL + row*136) + q*16;
        float s = 0.f;
        #pragma unroll
        for (int i = 0; i < 16; i++) {
            float2 a = __bfloat1622float2(ph[i]);
            float2 b = __bfloat1622float2(pl[i]);
            s += a.x + a.y + b.x + b.y;
        }
        s += __shfl_xor_sync(0xffffffffu, s, 1);
        s += __shfl_xor_sync(0xffffffffu, s, 2);
        if (q == 0) atomicAdd(g_ksum + nh*64 + row, s);
    }
}

// =================================================================
// k2: q projection + attention apply (proven @ R8)
// grid (LL/128, NHD), block 256, smem ~74KB -> 2 CTA/SM
// =================================================================
#define SO2_WQH 0
#define SO2_WQL 9216
#define SO2_KVH 18432
#define SO2_KVL 27648
#define SO2_XH  36864
#define SO2_XL  55296
#define SO2_KS  73728
#define SO2_ZB  73984
#define SMEM2M  74496

__global__ void __launch_bounds__(256, 2)
k2_mma(const float* __restrict__ x,
       const float* __restrict__ wq) {
    extern __shared__ char smem[];
    bf16* WQH = (bf16*)(smem + SO2_WQH);
    bf16* WQL = (bf16*)(smem + SO2_WQL);
    bf16* KVH = (bf16*)(smem + SO2_KVH);
    bf16* KVL = (bf16*)(smem + SO2_KVL);
    bf16* XH  = (bf16*)(smem + SO2_XH);
    bf16* XL  = (bf16*)(smem + SO2_XL);
    float* ksb = (float*)(smem + SO2_KS);
    float* zb  = (float*)(smem + SO2_ZB);

    int tid = threadIdx.x, lane = tid & 31, w = tid >> 5;
    int r = lane >> 2, c2 = (lane & 3)*2;
    int wM = w & 3, wN = w >> 2;
    int nh = blockIdx.y, n = nh >> 3, h = nh & 7;
    int l0 = blockIdx.x * 128;

    for (int i = tid; i < 4096; i += 256) {
        int e = i >> 6, d = i & 63;
        float v = wq[i];
        bf16 hh = __float2bfloat16(v);
        WQH[e*72 + d] = hh;
        WQL[e*72 + d] = __float2bfloat16(v - __bfloat162float(hh));
        int dk = i >> 6, dv = i & 63;
        float kvv = g_kv[nh*4096 + i];
        bf16 kh = __float2bfloat16(kvv);
        KVH[dv*72 + dk] = kh;
        KVL[dv*72 + dk] = __float2bfloat16(kvv - __bfloat162float(kh));
    }
    for (int i = tid; i < 4096; i += 256) {
        int t = i >> 5, j = (i & 31)*2;
        float2 xv = *(const float2*)(x + ((size_t)(n*LL + l0 + t)*HH + h)*64 + j);
        uint32_t hi, lo;
        split2(xv.x, xv.y, hi, lo);
        *(uint32_t*)(XH + t*72 + j) = hi;
        *(uint32_t*)(XL + t*72 + j) = lo;
    }
    if (tid < 64) ksb[tid] = g_ksum[nh*64 + tid];
    __syncthreads();

    float accQ[2][4][4];
    #pragma unroll
    for (int i = 0; i < 2; i++)
        #pragma unroll
        for (int j = 0; j < 4; j++)
            #pragma unroll
            for (int q = 0; q < 4; q++) accQ[i][j][q] = 0.f;
    warp_gemm<4,4>(accQ, XH, XL, 72, wM*32, WQH, WQL, 72, wN*32, lane);
    #pragma unroll
    for (int i = 0; i < 2; i++)
        #pragma unroll
        for (int j = 0; j < 4; j++)
            #pragma unroll
            for (int q = 0; q < 4; q++) accQ[i][j][q] = elu1(accQ[i][j][q]);
    __syncthreads();

    #pragma unroll
    for (int mt = 0; mt < 2; mt++)
        #pragma unroll
        for (int nt = 0; nt < 4; nt++) {
            int rr = wM*32 + mt*16 + r;
            int cc = wN*32 + nt*8 + c2;
            uint32_t hi, lo;
            split2(accQ[mt][nt][0], accQ[mt][nt][1], hi, lo);
            *(uint32_t*)(XH + rr*72 + cc) = hi;
            *(uint32_t*)(XL + rr*72 + cc) = lo;
            split2(accQ[mt][nt][2], accQ[mt][nt][3], hi, lo);
            *(uint32_t*)(XH + (rr+8)*72 + cc) = hi;
            *(uint32_t*)(XL + (rr+8)*72 + cc) = lo;
        }
    __syncthreads();

    if (tid < 128) {
        const __nv_bfloat162* ph = (const __nv_bfloat162*)(XH + tid*72);
        const __nv_bfloat162* pl = (const __nv_bfloat162*)(XL + tid*72);
        float s = 0.f;
        #pragma unroll 8
        for (int i = 0; i < 32; i++) {
            float2 a = __bfloat1622float2(ph[i]);
            float2 b = __bfloat1622float2(pl[i]);
            s += (a.x + b.x)*ksb[2*i] + (a.y + b.y)*ksb[2*i + 1];
        }
        zb[tid] = 1.f / (s + 1e-6f);
    }
    __syncthreads();

    float accM[2][4][4];
    #pragma unroll
    for (int i = 0; i < 2; i++)
        #pragma unroll
        for (int j = 0; j < 4; j++)
            #pragma unroll
            for (int q = 0; q < 4; q++) accM[i][j][q] = 0.f;
    warp_gemm<4,4>(accM, XH, XL, 72, wM*32, KVH, KVL, 72, wN*32, lane);
    #pragma unroll
    for (int mt = 0; mt < 2; mt++)
        #pragma unroll
        for (int nt = 0; nt < 4; nt++) {
            int rr = wM*32 + mt*16 + r;
            int cc = wN*32 + nt*8 + c2;
            float z0 = zb[rr], z1 = zb[rr + 8];
            size_t row0 = ((size_t)(n*LL + l0 + rr)*HH + h)*64;
            size_t row1 = ((size_t)(n*LL + l0 + rr + 8)*HH + h)*64;
            float2 o0 = {accM[mt][nt][0]*z0, accM[mt][nt][1]*z0};
            float2 o1 = {accM[mt][nt][2]*z1, accM[mt][nt][3]*z1};
            *(float2*)(g_msg + row0 + cc) = o0;
            *(float2*)(g_msg + row1 + cc) = o1;
        }
}

// =================================================================
// k3: merge+LN1+FFN+LN2+residual — now 512 threads (16 warps, 2x8)
// =================================================================
__device__ __forceinline__ void quad_reduce2(float& s, float& q) {
    s += __shfl_xor_sync(0xffffffffu, s, 1);
    q += __shfl_xor_sync(0xffffffffu, q, 1);
    s += __shfl_xor_sync(0xffffffffu, s, 2);
    q += __shfl_xor_sync(0xffffffffu, q, 2);
}

#define SO_W1H 0
#define SO_W1L 34816
#define SO_W2H 69632
#define SO_W2L 87040
#define SO_WMH 104448
#define SO_WML 113664
#define SO_HH  122880
#define SO_HL  140288
#define SO_H1H 157696
#define SO_H1L 175104
#define SO_XB  192512
#define SO_GB  209408
#define SO_PS  210432
#define SO_PQ  212480
#define SO_MEAN 214528
#define SO_INV 214784
#define SMEM3M 215040

__global__ void __launch_bounds__(512, 1)
k3_mma(const float* __restrict__ x,
       const float* __restrict__ wm,
       const float* __restrict__ w1,
       const float* __restrict__ w2,
       const float* __restrict__ g1, const float* __restrict__ b1,
       const float* __restrict__ g2, const float* __restrict__ b2,
       float* __restrict__ out) {
    extern __shared__ char smem[];
    bf16* W1H = (bf16*)(smem + SO_W1H);
    bf16* W1L = (bf16*)(smem + SO_W1L);
    bf16* W2H = (bf16*)(smem + SO_W2H);
    bf16* W2L = (bf16*)(smem + SO_W2L);
    bf16* WMH = (bf16*)(smem + SO_WMH);
    bf16* WML = (bf16*)(smem + SO_WML);
    bf16* Hh  = (bf16*)(smem + SO_HH);
    bf16* Hl  = (bf16*)(smem + SO_HL);
    bf16* H1h = (bf16*)(smem + SO_H1H);
    bf16* H1l = (bf16*)(smem + SO_H1L);
    float* xb    = (float*)(smem + SO_XB);
    float* gbuf  = (float*)(smem + SO_GB);
    float* ps    = (float*)(smem + SO_PS);     // [64][8]
    float* pq    = (float*)(smem + SO_PQ);
    float* means = (float*)(smem + SO_MEAN);
    float* invs  = (float*)(smem + SO_INV);

    int tid = threadIdx.x, lane = tid & 31, w = tid >> 5;
    int wM = w & 1, wN = w >> 1;   // 2 x 8 warp grid
    int r = lane >> 2, c2 = (lane & 3)*2;

    for (int i = tid; i < 16384; i += 512) {
        int nn = i >> 7, kk = i & 127;
        float v = w1[i];
        bf16 h = __float2bfloat16(v);
        W1H[nn*136 + kk] = h;
        W1L[nn*136 + kk] = __float2bfloat16(v - __bfloat162float(h));
    }
    for (int i = tid; i < 8192; i += 512) {
        int nn = i >> 7, kk = i & 127;
        float v = w2[i];
        bf16 h = __float2bfloat16(v);
        W2H[nn*136 + kk] = h;
        W2L[nn*136 + kk] = __float2bfloat16(v - __bfloat162float(h));
    }
    for (int i = tid; i < 4096; i += 512) {
        int nn = i >> 6, kk = i & 63;
        float v = wm[i];
        bf16 h = __float2bfloat16(v);
        WMH[nn*72 + kk] = h;
        WML[nn*72 + kk] = __float2bfloat16(v - __bfloat162float(h));
    }
    if (tid < 64) {
        gbuf[tid]       = g1[tid];
        gbuf[64 + tid]  = b1[tid];
        gbuf[128 + tid] = g2[tid];
        gbuf[192 + tid] = b2[tid];
    }
    __syncthreads();

    for (int tile = blockIdx.x; tile < NTOK/64; tile += gridDim.x) {
        int tok0 = tile * 64;

        for (int i = tid; i < 2048; i += 512) {
            int t = i >> 5, j = (i & 31)*2;
            float2 mv = *(const float2*)(g_msg + (size_t)(tok0 + t)*64 + j);
            uint32_t hi, lo;
            split2(mv.x, mv.y, hi, lo);
            *(uint32_t*)(H1h + t*136 + j) = hi;
            *(uint32_t*)(H1l + t*136 + j) = lo;
            float2 xv = *(const float2*)(x + (size_t)(tok0 + t)*64 + j);
            split2(xv.x, xv.y, hi, lo);
            *(uint32_t*)(Hh + t*136 + j) = hi;
            *(uint32_t*)(Hl + t*136 + j) = lo;
            *(float2*)(xb + t*66 + j) = xv;
        }
        __syncthreads();

        // ---- Stage A: msg @ wm^T  (M64,N64,K64); warp covers 8 cols ----
        float accA[2][1][4];
        #pragma unroll
        for (int i = 0; i < 2; i++)
            #pragma unroll
            for (int q = 0; q < 4; q++) accA[i][0][q] = 0.f;
        warp_gemm<1,4>(accA, H1h, H1l, 136, wM*32, WMH, WML, 72, wN*8, lane);

        // LN1 partial stats (8 cols per warp)
        #pragma unroll
        for (int mt = 0; mt < 2; mt++) {
            float a0 = accA[mt][0][0], a1 = accA[mt][0][1];
            float a2 = accA[mt][0][2], a3 = accA[mt][0][3];
            float s0 = a0 + a1, q0 = a0*a0 + a1*a1;
            float s1 = a2 + a3, q1 = a2*a2 + a3*a3;
            quad_reduce2(s0, q0);
            quad_reduce2(s1, q1);
            if ((lane & 3) == 0) {
                int rr = wM*32 + mt*16 + r;
                ps[rr*8 + wN] = s0;      pq[rr*8 + wN] = q0;
                ps[(rr+8)*8 + wN] = s1;  pq[(rr+8)*8 + wN] = q1;
            }
        }
        __syncthreads();
        if (tid < 64) {
            float s = 0.f, q = 0.f;
            #pragma unroll
            for (int o = 0; o < 8; o++) { s += ps[tid*8 + o]; q += pq[tid*8 + o]; }
            float mean = s * (1.f/64.f);
            float var  = q * (1.f/64.f) - mean*mean;
            means[tid] = mean;
            invs[tid]  = rsqrtf(var + 1e-5f);
        }
        __syncthreads();

        // apply LN1 -> H cols 64..127
        #pragma unroll
        for (int mt = 0; mt < 2; mt++) {
            int rr = wM*32 + mt*16 + r;
            int cc = wN*8 + c2;
            float m0 = means[rr], i0 = invs[rr];
            float y0 = (accA[mt][0][0] - m0)*i0*gbuf[cc]   + gbuf[64+cc];
            float y1 = (accA[mt][0][1] - m0)*i0*gbuf[cc+1] + gbuf[64+cc+1];
            uint32_t hi, lo;
            split2(y0, y1, hi, lo);
            *(uint32_t*)(Hh + rr*136 + 64 + cc) = hi;
            *(uint32_t*)(Hl + rr*136 + 64 + cc) = lo;
            float m1 = means[rr+8], i1 = invs[rr+8];
            float y2 = (accA[mt][0][2] - m1)*i1*gbuf[cc]   + gbuf[64+cc];
            float y3 = (accA[mt][0][3] - m1)*i1*gbuf[cc+1] + gbuf[64+cc+1];
            split2(y2, y3, hi, lo);
            *(uint32_t*)(Hh + (rr+8)*136 + 64 + cc) = hi;
            *(uint32_t*)(Hl + (rr+8)*136 + 64 + cc) = lo;
        }
        __syncthreads();

        // ---- Stage B: [x;m] @ w1^T  (M64,N128,K128); warp covers 16 cols ----
        float accB[2][2][4];
        #pragma unroll
        for (int i = 0; i < 2; i++)
            #pragma unroll
            for (int j = 0; j < 2; j++)
                #pragma unroll
                for (int q = 0; q < 4; q++) accB[i][j][q] = 0.f;
        warp_gemm<2,8>(accB, Hh, Hl, 136, wM*32, W1H, W1L, 136, wN*16, lane);

        #pragma unroll
        for (int mt = 0; mt < 2; mt++)
            #pragma unroll
            for (int nt = 0; nt < 2; nt++) {
                int rr = wM*32 + mt*16 + r;
                int cc = wN*16 + nt*8 + c2;
                uint32_t hi, lo;
                split2(fmaxf(accB[mt][nt][0], 0.f), fmaxf(accB[mt][nt][1], 0.f), hi, lo);
                *(uint32_t*)(H1h + rr*136 + cc) = hi;
                *(uint32_t*)(H1l + rr*136 + cc) = lo;
                split2(fmaxf(accB[mt][nt][2], 0.f), fmaxf(accB[mt][nt][3], 0.f), hi, lo);
                *(uint32_t*)(H1h + (rr+8)*136 + cc) = hi;
                *(uint32_t*)(H1l + (rr+8)*136 + cc) = lo;
            }
        __syncthreads();

        // ---- Stage C: h1 @ w2^T  (M64,N64,K128); warp covers 8 cols ----
        float accC[2][1][4];
        #pragma unroll
        for (int i = 0; i < 2; i++)
            #pragma unroll
            for (int q = 0; q < 4; q++) accC[i][0][q] = 0.f;
        warp_gemm<1,8>(accC, H1h, H1l, 136, wM*32, W2H, W2L, 136, wN*8, lane);

        // LN2 partial stats
        #pragma unroll
        for (int mt = 0; mt < 2; mt++) {
            float a0 = accC[mt][0][0], a1 = accC[mt][0][1];
            float a2 = accC[mt][0][2], a3 = accC[mt][0][3];
            float s0 = a0 + a1, q0 = a0*a0 + a1*a1;
            float s1 = a2 + a3, q1 = a2*a2 + a3*a3;
            quad_reduce2(s0, q0);
            quad_reduce2(s1, q1);
            if ((lane & 3) == 0) {
                int rr = wM*32 + mt*16 + r;
                ps[rr*8 + wN] = s0;      pq[rr*8 + wN] = q0;
                ps[(rr+8)*8 + wN] = s1;  pq[(rr+8)*8 + wN] = q1;
            }
        }
        __syncthreads();
        if (tid < 64) {
            float s = 0.f, q = 0.f;
            #pragma unroll
            for (int o = 0; o < 8; o++) { s += ps[tid*8 + o]; q += pq[tid*8 + o]; }
            float mean = s * (1.f/64.f);
            float var  = q * (1.f/64.f) - mean*mean;
            means[tid] = mean;
            invs[tid]  = rsqrtf(var + 1e-5f);
        }
        __syncthreads();

        // LN2 + residual -> gmem
        #pragma unroll
        for (int mt = 0; mt < 2; mt++) {
            int rr = wM*32 + mt*16 + r;
            int cc = wN*8 + c2;
            float m0 = means[rr], i0 = invs[rr];
            float2 xv = *(const float2*)(xb + rr*66 + cc);
            float2 o0;
            o0.x = xv.x + (accC[mt][0][0] - m0)*i0*gbuf[128+cc]   + gbuf[192+cc];
            o0.y = xv.y + (accC[mt][0][1] - m0)*i0*gbuf[128+cc+1] + gbuf[192+cc+1];
            *(float2*)(out + (size_t)(tok0 + rr)*64 + cc) = o0;
            float m1 = means[rr+8], i1 = invs[rr+8];
            float2 xw = *(const float2*)(xb + (rr+8)*66 + cc);
            float2 o1;
            o1.x = xw.x + (accC[mt][0][2] - m1)*i1*gbuf[128+cc]   + gbuf[192+cc];
            o1.y = xw.y + (accC[mt][0][3] - m1)*i1*gbuf[128+cc+1] + gbuf[192+cc+1];
            *(float2*)(out + (size_t)(tok0 + rr + 8)*64 + cc) = o1;
        }
        __syncthreads();
    }
}

// ---------------- launch ----------------
extern "C" void kernel_launch(void* const* d_in, const int* in_sizes, int n_in,
                              void* d_out, int out_size) {
    const float* x   = (const float*)d_in[0];
    const float* src = (const float*)d_in[1];
    const float* wq  = (const float*)d_in[2];
    const float* wk  = (const float*)d_in[3];
    const float* wv  = (const float*)d_in[4];
    const float* wm  = (const float*)d_in[5];
    const float* w1  = (const float*)d_in[6];
    const float* w2  = (const float*)d_in[7];
    const float* g1  = (const float*)d_in[8];
    const float* b1  = (const float*)d_in[9];
    const float* g2  = (const float*)d_in[10];
    const float* b2  = (const float*)d_in[11];
    float* out = (float*)d_out;

    cudaFuncSetAttribute(k1_mma, cudaFuncAttributeMaxDynamicSharedMemorySize, SMEM1M);
    cudaFuncSetAttribute(k2_mma, cudaFuncAttributeMaxDynamicSharedMemorySize, SMEM2M);
    cudaFuncSetAttribute(k3_mma, cudaFuncAttributeMaxDynamicSharedMemorySize, SMEM3M);

    k0_zero<<<512, 256>>>();
    k1_mma<<<dim3(SS/128, NHD), 256, SMEM1M>>>(src, wk, wv);
    k2_mma<<<dim3(LL/128, NHD), 256, SMEM2M>>>(x, wq);
    k3_mma<<<148, 512, SMEM3M>>>(x, wm, w1, w2, g1, b1, g2, b2, out);
}

// round 14
// speedup vs baseline: 1.4329x; 1.3408x over previous
#include <cuda_runtime.h>
#include <cuda_bf16.h>
#include <math.h>
#include <stdint.h>

#define NB 4
#define LL 4096
#define SS 4096
#define HH 8
#define NHD 32
#define NTOK (NB*LL*HH)    // 131072

typedef __nv_bfloat16 bf16;

// ---------------- scratch ----------------
__device__ float g_kv[NHD*64*64];
__device__ float g_ksum[NHD*64];
__device__ float g_msg[NTOK*64];

// ---------------- k0 ----------------
__global__ void k0_zero() {
    int i = blockIdx.x * blockDim.x + threadIdx.x;
    if (i < NHD*64*64) g_kv[i] = 0.f;
    if (i < NHD*64)    g_ksum[i] = 0.f;
}

// ================= mma helpers =================
__device__ __forceinline__ void mma_bf16(float d[4], const uint32_t a[4],
                                         uint32_t b0, uint32_t b1) {
    asm volatile("mma.sync.aligned.m16n8k16.row.col.f32.bf16.bf16.f32 "
        "{%0,%1,%2,%3}, {%4,%5,%6,%7}, {%8,%9}, {%0,%1,%2,%3};"
        : "+f"(d[0]), "+f"(d[1]), "+f"(d[2]), "+f"(d[3])
        : "r"(a[0]), "r"(a[1]), "r"(a[2]), "r"(a[3]), "r"(b0), "r"(b1));
}

__device__ __forceinline__ void split2(float v0, float v1, uint32_t& hi, uint32_t& lo) {
    bf16 h0 = __float2bfloat16(v0);
    bf16 h1 = __float2bfloat16(v1);
    __nv_bfloat162 hh = __halves2bfloat162(h0, h1);
    hi = *(uint32_t*)&hh;
    __nv_bfloat162 ll = __halves2bfloat162(
        __float2bfloat16(v0 - __bfloat162float(h0)),
        __float2bfloat16(v1 - __bfloat162float(h1)));
    lo = *(uint32_t*)&ll;
}

// warp GEMM: M32 (2 mtiles), N = NT*8, K = NK*16, 3-term bf16 split
template<int NT, int NK>
__device__ __forceinline__ void warp_gemm(float acc[2][NT][4],
    const bf16* __restrict__ Ah, const bf16* __restrict__ Al, int sa, int mrow0,
    const bf16* __restrict__ Bh, const bf16* __restrict__ Bl, int sb, int ncol0,
    int lane)
{
    int r = lane >> 2, c2 = (lane & 3)*2;
    #pragma unroll
    for (int ks = 0; ks < NK; ks++) {
        uint32_t ah[2][4], al[2][4];
        #pragma unroll
        for (int mt = 0; mt < 2; mt++) {
            const bf16* pa = Ah + (mrow0 + mt*16 + r)*sa + ks*16 + c2;
            const bf16* pl = Al + (mrow0 + mt*16 + r)*sa + ks*16 + c2;
            ah[mt][0] = *(const uint32_t*)(pa);
            ah[mt][1] = *(const uint32_t*)(pa + 8*sa);
            ah[mt][2] = *(const uint32_t*)(pa + 8);
            ah[mt][3] = *(const uint32_t*)(pa + 8*sa + 8);
            al[mt][0] = *(const uint32_t*)(pl);
            al[mt][1] = *(const uint32_t*)(pl + 8*sa);
            al[mt][2] = *(const uint32_t*)(pl + 8);
            al[mt][3] = *(const uint32_t*)(pl + 8*sa + 8);
        }
        #pragma unroll
        for (int nt = 0; nt < NT; nt++) {
            const bf16* pbh = Bh + (ncol0 + nt*8 + r)*sb + ks*16 + c2;
            const bf16* pbl = Bl + (ncol0 + nt*8 + r)*sb + ks*16 + c2;
            uint32_t bh0 = *(const uint32_t*)(pbh);
            uint32_t bh1 = *(const uint32_t*)(pbh + 8);
            uint32_t bl0 = *(const uint32_t*)(pbl);
            uint32_t bl1 = *(const uint32_t*)(pbl + 8);
            #pragma unroll
            for (int mt = 0; mt < 2; mt++) {
                mma_bf16(acc[mt][nt], ah[mt], bh0, bh1);
                mma_bf16(acc[mt][nt], ah[mt], bl0, bl1);
                mma_bf16(acc[mt][nt], al[mt], bh0, bh1);
            }
        }
    }
}

__device__ __forceinline__ float elu1(float v) {
    return (v > 0.f) ? (v + 1.f) : expf(v);
}

// =================================================================
// k1: kT/vT projection + kv outer product; 256 s per block (2 subs)
// grid (SS/256, NHD), block 256, smem 108.5KB -> 2 CTA/SM
// =================================================================
#define SO1_WKH 0
#define SO1_WKL 9216
#define SO1_WVH 18432
#define SO1_WVL 27648
#define SO1_SRH 36864
#define SO1_SRL 55296
#define SO1_KTH 73728
#define SO1_KTL 91136
#define SO1_VTH 36864          // alias over SRH
#define SO1_VTL 55296          // alias over SRL
#define SMEM1M  108544

__global__ void __launch_bounds__(256, 2)
k1_mma(const float* __restrict__ src,
       const float* __restrict__ wk,
       const float* __restrict__ wv) {
    extern __shared__ char smem[];
    bf16* WKH = (bf16*)(smem + SO1_WKH);
    bf16* WKL = (bf16*)(smem + SO1_WKL);
    bf16* WVH = (bf16*)(smem + SO1_WVH);
    bf16* WVL = (bf16*)(smem + SO1_WVL);
    bf16* SRH = (bf16*)(smem + SO1_SRH);   // src [s=128][d=64] stride 72
    bf16* SRL = (bf16*)(smem + SO1_SRL);
    bf16* KTH = (bf16*)(smem + SO1_KTH);   // kT [dk=64][s=128] stride 136
    bf16* KTL = (bf16*)(smem + SO1_KTL);
    bf16* VTH = (bf16*)(smem + SO1_VTH);   // vT aliases src
    bf16* VTL = (bf16*)(smem + SO1_VTL);

    int tid = threadIdx.x, lane = tid & 31, w = tid >> 5;
    int r = lane >> 2, c2 = (lane & 3)*2;
    int nh = blockIdx.y, n = nh >> 3, h = nh & 7;
    int wM = w & 1, wN = w >> 1;   // 2 x 4

    for (int i = tid; i < 4096; i += 256) {
        int e = i >> 6, d = i & 63;
        float vk = wk[i], vv = wv[i];
        bf16 hk = __float2bfloat16(vk);
        WKH[e*72 + d] = hk;
        WKL[e*72 + d] = __float2bfloat16(vk - __bfloat162float(hk));
        bf16 hv = __float2bfloat16(vv);
        WVH[e*72 + d] = hv;
        WVL[e*72 + d] = __float2bfloat16(vv - __bfloat162float(hv));
    }

    // outer-product accumulator + ksum, carried across subs (K grows 128->256)
    int wK = w >> 2, wM2 = (w >> 1) & 1, wN2 = w & 1;
    float accO[2][4][4];
    #pragma unroll
    for (int i = 0; i < 2; i++)
        #pragma unroll
        for (int j = 0; j < 4; j++)
            #pragma unroll
            for (int q = 0; q < 4; q++) accO[i][j][q] = 0.f;
    float kreg = 0.f;

    for (int sub = 0; sub < 2; sub++) {
        int s0 = blockIdx.x*256 + sub*128;
        __syncthreads();   // prior KT/VT reads done (iter>0); weight stores visible (iter 0)

        for (int i = tid; i < 4096; i += 256) {
            int t = i >> 5, j = (i & 31)*2;
            float2 sv = *(const float2*)(src + ((size_t)(n*SS + s0 + t)*HH + h)*64 + j);
            uint32_t hi, lo;
            split2(sv.x, sv.y, hi, lo);
            *(uint32_t*)(SRH + t*72 + j) = hi;
            *(uint32_t*)(SRL + t*72 + j) = lo;
        }
        __syncthreads();

        // ---- proj K (flipped): kT[e][s] = wk @ src^T  (M=64, N=128, K=64) ----
        {
            float accK[2][4][4];
            #pragma unroll
            for (int i = 0; i < 2; i++)
                #pragma unroll
                for (int j = 0; j < 4; j++)
                    #pragma unroll
                    for (int q = 0; q < 4; q++) accK[i][j][q] = 0.f;
            warp_gemm<4,4>(accK, WKH, WKL, 72, wM*32, SRH, SRL, 72, wN*32, lane);
            // write KT immediately (separate region; frees accK)
            #pragma unroll
            for (int mt = 0; mt < 2; mt++)
                #pragma unroll
                for (int nt = 0; nt < 4; nt++) {
                    int rr = wM*32 + mt*16 + r;
                    int cc = wN*32 + nt*8 + c2;
                    uint32_t hi, lo;
                    split2(elu1(accK[mt][nt][0]), elu1(accK[mt][nt][1]), hi, lo);
                    *(uint32_t*)(KTH + rr*136 + cc) = hi;
                    *(uint32_t*)(KTL + rr*136 + cc) = lo;
                    split2(elu1(accK[mt][nt][2]), elu1(accK[mt][nt][3]), hi, lo);
                    *(uint32_t*)(KTH + (rr+8)*136 + cc) = hi;
                    *(uint32_t*)(KTL + (rr+8)*136 + cc) = lo;
                }
        }

        // ---- proj V; acc held in regs across the sync ----
        {
            float accV[2][4][4];
            #pragma unroll
            for (int i = 0; i < 2; i++)
                #pragma unroll
                for (int j = 0; j < 4; j++)
                    #pragma unroll
                    for (int q = 0; q < 4; q++) accV[i][j][q] = 0.f;
            warp_gemm<4,4>(accV, WVH, WVL, 72, wM*32, SRH, SRL, 72, wN*32, lane);
            __syncthreads();   // all SR reads complete
            #pragma unroll
            for (int mt = 0; mt < 2; mt++)
                #pragma unroll
                for (int nt = 0; nt < 4; nt++) {
                    int rr = wM*32 + mt*16 + r;
                    int cc = wN*32 + nt*8 + c2;
                    uint32_t hi, lo;
                    split2(accV[mt][nt][0], accV[mt][nt][1], hi, lo);
                    *(uint32_t*)(VTH + rr*136 + cc) = hi;
                    *(uint32_t*)(VTL + rr*136 + cc) = lo;
                    split2(accV[mt][nt][2], accV[mt][nt][3], hi, lo);
                    *(uint32_t*)(VTH + (rr+8)*136 + cc) = hi;
                    *(uint32_t*)(VTL + (rr+8)*136 + cc) = lo;
                }
        }
        __syncthreads();

        // ---- outer: kv[dk][dv] += kT @ vT^T  (M=64, N=64, K=128 split x2) ----
        warp_gemm<4,4>(accO, KTH + wK*64, KTL + wK*64, 136, wM2*32,
                             VTH + wK*64, VTL + wK*64, 136, wN2*32, lane);

        // ---- ksum partial (4 threads per dk row) ----
        {
            int row = tid >> 2, q = tid & 3;
            const __nv_bfloat162* ph = (const __nv_bfloat162*)(KTH + row*136) + q*16;
            const __nv_bfloat162* pl = (const __nv_bfloat162*)(KTL + row*136) + q*16;
            float s = 0.f;
            #pragma unroll
            for (int i = 0; i < 16; i++) {
                float2 a = __bfloat1622float2(ph[i]);
                float2 b = __bfloat1622float2(pl[i]);
                s += a.x + a.y + b.x + b.y;
            }
            kreg += s;
        }
    }

    // ---- global accumulation (once per block) ----
    {
        float* kvg = g_kv + nh*4096;
        #pragma unroll
        for (int mt = 0; mt < 2; mt++)
            #pragma unroll
            for (int nt = 0; nt < 4; nt++) {
                int rr = wM2*32 + mt*16 + r;
                int cc = wN2*32 + nt*8 + c2;
                atomicAdd(kvg + rr*64 + cc,       accO[mt][nt][0]);
                atomicAdd(kvg + rr*64 + cc + 1,   accO[mt][nt][1]);
                atomicAdd(kvg + (rr+8)*64 + cc,   accO[mt][nt][2]);
                atomicAdd(kvg + (rr+8)*64 + cc+1, accO[mt][nt][3]);
            }
    }
    {
        int row = tid >> 2, q = tid & 3;
        kreg += __shfl_xor_sync(0xffffffffu, kreg, 1);
        kreg += __shfl_xor_sync(0xffffffffu, kreg, 2);
        if (q == 0) atomicAdd(g_ksum + nh*64 + row, kreg);
    }
}

// =================================================================
// k2: q projection + attention apply; 256 l per block (2 subs)
// grid (LL/256, NHD), block 256, smem ~74KB -> 2 CTA/SM
// =================================================================
#define SO2_WQH 0
#define SO2_WQL 9216
#define SO2_KVH 18432
#define SO2_KVL 27648
#define SO2_XH  36864
#define SO2_XL  55296
#define SO2_KS  73728
#define SO2_ZB  73984
#define SMEM2M  74496

__global__ void __launch_bounds__(256, 2)
k2_mma(const float* __restrict__ x,
       const float* __restrict__ wq) {
    extern __shared__ char smem[];
    bf16* WQH = (bf16*)(smem + SO2_WQH);
    bf16* WQL = (bf16*)(smem + SO2_WQL);
    bf16* KVH = (bf16*)(smem + SO2_KVH);
    bf16* KVL = (bf16*)(smem + SO2_KVL);
    bf16* XH  = (bf16*)(smem + SO2_XH);
    bf16* XL  = (bf16*)(smem + SO2_XL);
    float* ksb = (float*)(smem + SO2_KS);
    float* zb  = (float*)(smem + SO2_ZB);

    int tid = threadIdx.x, lane = tid & 31, w = tid >> 5;
    int r = lane >> 2, c2 = (lane & 3)*2;
    int wM = w & 3, wN = w >> 2;
    int nh = blockIdx.y, n = nh >> 3, h = nh & 7;

    for (int i = tid; i < 4096; i += 256) {
        int e = i >> 6, d = i & 63;
        float v = wq[i];
        bf16 hh = __float2bfloat16(v);
        WQH[e*72 + d] = hh;
        WQL[e*72 + d] = __float2bfloat16(v - __bfloat162float(hh));
        int dk = i >> 6, dv = i & 63;
        float kvv = g_kv[nh*4096 + i];
        bf16 kh = __float2bfloat16(kvv);
        KVH[dv*72 + dk] = kh;
        KVL[dv*72 + dk] = __float2bfloat16(kvv - __bfloat162float(kh));
    }
    if (tid < 64) ksb[tid] = g_ksum[nh*64 + tid];

    for (int sub = 0; sub < 2; sub++) {
        int l0 = blockIdx.x*256 + sub*128;
        __syncthreads();   // prior X reads done (iter>0); weight/kv visible (iter 0)

        for (int i = tid; i < 4096; i += 256) {
            int t = i >> 5, j = (i & 31)*2;
            float2 xv = *(const float2*)(x + ((size_t)(n*LL + l0 + t)*HH + h)*64 + j);
            uint32_t hi, lo;
            split2(xv.x, xv.y, hi, lo);
            *(uint32_t*)(XH + t*72 + j) = hi;
            *(uint32_t*)(XL + t*72 + j) = lo;
        }
        __syncthreads();

        float accQ[2][4][4];
        #pragma unroll
        for (int i = 0; i < 2; i++)
            #pragma unroll
            for (int j = 0; j < 4; j++)
                #pragma unroll
                for (int q = 0; q < 4; q++) accQ[i][j][q] = 0.f;
        warp_gemm<4,4>(accQ, XH, XL, 72, wM*32, WQH, WQL, 72, wN*32, lane);
        #pragma unroll
        for (int i = 0; i < 2; i++)
            #pragma unroll
            for (int j = 0; j < 4; j++)
                #pragma unroll
                for (int q = 0; q < 4; q++) accQ[i][j][q] = elu1(accQ[i][j][q]);
        __syncthreads();

        #pragma unroll
        for (int mt = 0; mt < 2; mt++)
            #pragma unroll
            for (int nt = 0; nt < 4; nt++) {
                int rr = wM*32 + mt*16 + r;
                int cc = wN*32 + nt*8 + c2;
                uint32_t hi, lo;
                split2(accQ[mt][nt][0], accQ[mt][nt][1], hi, lo);
                *(uint32_t*)(XH + rr*72 + cc) = hi;
                *(uint32_t*)(XL + rr*72 + cc) = lo;
                split2(accQ[mt][nt][2], accQ[mt][nt][3], hi, lo);
                *(uint32_t*)(XH + (rr+8)*72 + cc) = hi;
                *(uint32_t*)(XL + (rr+8)*72 + cc) = lo;
            }
        __syncthreads();

        if (tid < 128) {
            const __nv_bfloat162* ph = (const __nv_bfloat162*)(XH + tid*72);
            const __nv_bfloat162* pl = (const __nv_bfloat162*)(XL + tid*72);
            float s = 0.f;
            #pragma unroll 8
            for (int i = 0; i < 32; i++) {
                float2 a = __bfloat1622float2(ph[i]);
                float2 b = __bfloat1622float2(pl[i]);
                s += (a.x + b.x)*ksb[2*i] + (a.y + b.y)*ksb[2*i + 1];
            }
            zb[tid] = 1.f / (s + 1e-6f);
        }
        __syncthreads();

        float accM[2][4][4];
        #pragma unroll
        for (int i = 0; i < 2; i++)
            #pragma unroll
            for (int j = 0; j < 4; j++)
                #pragma unroll
                for (int q = 0; q < 4; q++) accM[i][j][q] = 0.f;
        warp_gemm<4,4>(accM, XH, XL, 72, wM*32, KVH, KVL, 72, wN*32, lane);
        #pragma unroll
        for (int mt = 0; mt < 2; mt++)
            #pragma unroll
            for (int nt = 0; nt < 4; nt++) {
                int rr = wM*32 + mt*16 + r;
                int cc = wN*32 + nt*8 + c2;
                float z0 = zb[rr], z1 = zb[rr + 8];
                size_t row0 = ((size_t)(n*LL + l0 + rr)*HH + h)*64;
                size_t row1 = ((size_t)(n*LL + l0 + rr + 8)*HH + h)*64;
                float2 o0 = {accM[mt][nt][0]*z0, accM[mt][nt][1]*z0};
                float2 o1 = {accM[mt][nt][2]*z1, accM[mt][nt][3]*z1};
                *(float2*)(g_msg + row0 + cc) = o0;
                *(float2*)(g_msg + row1 + cc) = o1;
            }
    }
}

// =================================================================
// k3: merge+LN1+FFN+LN2+residual — 256 threads (proven 114us @ R7/R8)
// =================================================================
__device__ __forceinline__ void quad_reduce2(float& s, float& q) {
    s += __shfl_xor_sync(0xffffffffu, s, 1);
    q += __shfl_xor_sync(0xffffffffu, q, 1);
    s += __shfl_xor_sync(0xffffffffu, s, 2);
    q += __shfl_xor_sync(0xffffffffu, q, 2);
}

#define SO_W1H 0
#define SO_W1L 34816
#define SO_W2H 69632
#define SO_W2L 87040
#define SO_WMH 104448
#define SO_WML 113664
#define SO_HH  122880
#define SO_HL  140288
#define SO_H1H 157696
#define SO_H1L 175104
#define SO_XB  192512
#define SO_GB  209408
#define SO_PS  210432
#define SO_PQ  211456
#define SO_MEAN 212480
#define SO_INV 212736
#define SMEM3M 212992

__global__ void __launch_bounds__(256, 1)
k3_mma(const float* __restrict__ x,
       const float* __restrict__ wm,
       const float* __restrict__ w1,
       const float* __restrict__ w2,
       const float* __restrict__ g1, const float* __restrict__ b1,
       const float* __restrict__ g2, const float* __restrict__ b2,
       float* __restrict__ out) {
    extern __shared__ char smem[];
    bf16* W1H = (bf16*)(smem + SO_W1H);
    bf16* W1L = (bf16*)(smem + SO_W1L);
    bf16* W2H = (bf16*)(smem + SO_W2H);
    bf16* W2L = (bf16*)(smem + SO_W2L);
    bf16* WMH = (bf16*)(smem + SO_WMH);
    bf16* WML = (bf16*)(smem + SO_WML);
    bf16* Hh  = (bf16*)(smem + SO_HH);
    bf16* Hl  = (bf16*)(smem + SO_HL);
    bf16* H1h = (bf16*)(smem + SO_H1H);
    bf16* H1l = (bf16*)(smem + SO_H1L);
    float* xb    = (float*)(smem + SO_XB);
    float* gbuf  = (float*)(smem + SO_GB);
    float* ps    = (float*)(smem + SO_PS);
    float* pq    = (float*)(smem + SO_PQ);
    float* means = (float*)(smem + SO_MEAN);
    float* invs  = (float*)(smem + SO_INV);

    int tid = threadIdx.x, lane = tid & 31, w = tid >> 5;
    int wM = w & 1, wN = w >> 1;
    int r = lane >> 2, c2 = (lane & 3)*2;

    for (int i = tid; i < 16384; i += 256) {
        int nn = i >> 7, kk = i & 127;
        float v = w1[i];
        bf16 h = __float2bfloat16(v);
        W1H[nn*136 + kk] = h;
        W1L[nn*136 + kk] = __float2bfloat16(v - __bfloat162float(h));
    }
    for (int i = tid; i < 8192; i += 256) {
        int nn = i >> 7, kk = i & 127;
        float v = w2[i];
        bf16 h = __float2bfloat16(v);
        W2H[nn*136 + kk] = h;
        W2L[nn*136 + kk] = __float2bfloat16(v - __bfloat162float(h));
    }
    for (int i = tid; i < 4096; i += 256) {
        int nn = i >> 6, kk = i & 63;
        float v = wm[i];
        bf16 h = __float2bfloat16(v);
        WMH[nn*72 + kk] = h;
        WML[nn*72 + kk] = __float2bfloat16(v - __bfloat162float(h));
    }
    if (tid < 64) {
        gbuf[tid]       = g1[tid];
        gbuf[64 + tid]  = b1[tid];
        gbuf[128 + tid] = g2[tid];
        gbuf[192 + tid] = b2[tid];
    }
    __syncthreads();

    for (int tile = blockIdx.x; tile < NTOK/64; tile += gridDim.x) {
        int tok0 = tile * 64;

        for (int i = tid; i < 2048; i += 256) {
            int t = i >> 5, j = (i & 31)*2;
            float2 mv = *(const float2*)(g_msg + (size_t)(tok0 + t)*64 + j);
            uint32_t hi, lo;
            split2(mv.x, mv.y, hi, lo);
            *(uint32_t*)(H1h + t*136 + j) = hi;
            *(uint32_t*)(H1l + t*136 + j) = lo;
            float2 xv = *(const float2*)(x + (size_t)(tok0 + t)*64 + j);
            split2(xv.x, xv.y, hi, lo);
            *(uint32_t*)(Hh + t*136 + j) = hi;
            *(uint32_t*)(Hl + t*136 + j) = lo;
            *(float2*)(xb + t*66 + j) = xv;
        }
        __syncthreads();

        float accA[2][2][4];
        #pragma unroll
        for (int i = 0; i < 2; i++)
            #pragma unroll
            for (int j = 0; j < 2; j++)
                #pragma unroll
                for (int q = 0; q < 4; q++) accA[i][j][q] = 0.f;
        warp_gemm<2,4>(accA, H1h, H1l, 136, wM*32, WMH, WML, 72, wN*16, lane);

        #pragma unroll
        for (int mt = 0; mt < 2; mt++) {
            float s0 = 0.f, q0 = 0.f, s1 = 0.f, q1 = 0.f;
            #pragma unroll
            for (int nt = 0; nt < 2; nt++) {
                float a0 = accA[mt][nt][0], a1 = accA[mt][nt][1];
                float a2 = accA[mt][nt][2], a3 = accA[mt][nt][3];
                s0 += a0 + a1; q0 += a0*a0 + a1*a1;
                s1 += a2 + a3; q1 += a2*a2 + a3*a3;
            }
            quad_reduce2(s0, q0);
            quad_reduce2(s1, q1);
            if ((lane & 3) == 0) {
                int rr = wM*32 + mt*16 + r;
                ps[rr*4 + wN] = s0;      pq[rr*4 + wN] = q0;
                ps[(rr+8)*4 + wN] = s1;  pq[(rr+8)*4 + wN] = q1;
            }
        }
        __syncthreads();
        if (tid < 64) {
            float s = ps[tid*4] + ps[tid*4+1] + ps[tid*4+2] + ps[tid*4+3];
            float q = pq[tid*4] + pq[tid*4+1] + pq[tid*4+2] + pq[tid*4+3];
            float mean = s * (1.f/64.f);
            float var  = q * (1.f/64.f) - mean*mean;
            means[tid] = mean;
            invs[tid]  = rsqrtf(var + 1e-5f);
        }
        __syncthreads();

        #pragma unroll
        for (int mt = 0; mt < 2; mt++)
            #pragma unroll
            for (int nt = 0; nt < 2; nt++) {
                int rr = wM*32 + mt*16 + r;
                int cc = wN*16 + nt*8 + c2;
                float m0 = means[rr], i0 = invs[rr];
                float y0 = (accA[mt][nt][0] - m0)*i0*gbuf[cc]   + gbuf[64+cc];
                float y1 = (accA[mt][nt][1] - m0)*i0*gbuf[cc+1] + gbuf[64+cc+1];
                uint32_t hi, lo;
                split2(y0, y1, hi, lo);
                *(uint32_t*)(Hh + rr*136 + 64 + cc) = hi;
                *(uint32_t*)(Hl + rr*136 + 64 + cc) = lo;
                float m1 = means[rr+8], i1 = invs[rr+8];
                float y2 = (accA[mt][nt][2] - m1)*i1*gbuf[cc]   + gbuf[64+cc];
                float y3 = (accA[mt][nt][3] - m1)*i1*gbuf[cc+1] + gbuf[64+cc+1];
                split2(y2, y3, hi, lo);
                *(uint32_t*)(Hh + (rr+8)*136 + 64 + cc) = hi;
                *(uint32_t*)(Hl + (rr+8)*136 + 64 + cc) = lo;
            }
        __syncthreads();

        float accB[2][4][4];
        #pragma unroll
        for (int i = 0; i < 2; i++)
            #pragma unroll
            for (int j = 0; j < 4; j++)
                #pragma unroll
                for (int q = 0; q < 4; q++) accB[i][j][q] = 0.f;
        warp_gemm<4,8>(accB, Hh, Hl, 136, wM*32, W1H, W1L, 136, wN*32, lane);

        #pragma unroll
        for (int mt = 0; mt < 2; mt++)
            #pragma unroll
            for (int nt = 0; nt < 4; nt++) {
                int rr = wM*32 + mt*16 + r;
                int cc = wN*32 + nt*8 + c2;
                uint32_t hi, lo;
                split2(fmaxf(accB[mt][nt][0], 0.f), fmaxf(accB[mt][nt][1], 0.f), hi, lo);
                *(uint32_t*)(H1h + rr*136 + cc) = hi;
                *(uint32_t*)(H1l + rr*136 + cc) = lo;
                split2(fmaxf(accB[mt][nt][2], 0.f), fmaxf(accB[mt][nt][3], 0.f), hi, lo);
                *(uint32_t*)(H1h + (rr+8)*136 + cc) = hi;
                *(uint32_t*)(H1l + (rr+8)*136 + cc) = lo;
            }
        __syncthreads();

        float accC[2][2][4];
        #pragma unroll
        for (int i = 0; i < 2; i++)
            #pragma unroll
            for (int j = 0; j < 2; j++)
                #pragma unroll
                for (int q = 0; q < 4; q++) accC[i][j][q] = 0.f;
        warp_gemm<2,8>(accC, H1h, H1l, 136, wM*32, W2H, W2L, 136, wN*16, lane);

        #pragma unroll
        for (int mt = 0; mt < 2; mt++) {
            float s0 = 0.f, q0 = 0.f, s1 = 0.f, q1 = 0.f;
            #pragma unroll
            for (int nt = 0; nt < 2; nt++) {
                float a0 = accC[mt][nt][0], a1 = accC[mt][nt][1];
                float a2 = accC[mt][nt][2], a3 = accC[mt][nt][3];
                s0 += a0 + a1; q0 += a0*a0 + a1*a1;
                s1 += a2 + a3; q1 += a2*a2 + a3*a3;
            }
            quad_reduce2(s0, q0);
            quad_reduce2(s1, q1);
            if ((lane & 3) == 0) {
                int rr = wM*32 + mt*16 + r;
                ps[rr*4 + wN] = s0;      pq[rr*4 + wN] = q0;
                ps[(rr+8)*4 + wN] = s1;  pq[(rr+8)*4 + wN] = q1;
            }
        }
        __syncthreads();
        if (tid < 64) {
            float s = ps[tid*4] + ps[tid*4+1] + ps[tid*4+2] + ps[tid*4+3];
            float q = pq[tid*4] + pq[tid*4+1] + pq[tid*4+2] + pq[tid*4+3];
            float mean = s * (1.f/64.f);
            float var  = q * (1.f/64.f) - mean*mean;
            means[tid] = mean;
            invs[tid]  = rsqrtf(var + 1e-5f);
        }
        __syncthreads();

        #pragma unroll
        for (int mt = 0; mt < 2; mt++)
            #pragma unroll
            for (int nt = 0; nt < 2; nt++) {
                int rr = wM*32 + mt*16 + r;
                int cc = wN*16 + nt*8 + c2;
                float m0 = means[rr], i0 = invs[rr];
                float2 xv = *(const float2*)(xb + rr*66 + cc);
                float2 o0;
                o0.x = xv.x + (accC[mt][nt][0] - m0)*i0*gbuf[128+cc]   + gbuf[192+cc];
                o0.y = xv.y + (accC[mt][nt][1] - m0)*i0*gbuf[128+cc+1] + gbuf[192+cc+1];
                *(float2*)(out + (size_t)(tok0 + rr)*64 + cc) = o0;
                float m1 = means[rr+8], i1 = invs[rr+8];
                float2 xw = *(const float2*)(xb + (rr+8)*66 + cc);
                float2 o1;
                o1.x = xw.x + (accC[mt][nt][2] - m1)*i1*gbuf[128+cc]   + gbuf[192+cc];
                o1.y = xw.y + (accC[mt][nt][3] - m1)*i1*gbuf[128+cc+1] + gbuf[192+cc+1];
                *(float2*)(out + (size_t)(tok0 + rr + 8)*64 + cc) = o1;
            }
        __syncthreads();
    }
}

// ---------------- launch ----------------
extern "C" void kernel_launch(void* const* d_in, const int* in_sizes, int n_in,
                              void* d_out, int out_size) {
    const float* x   = (const float*)d_in[0];
    const float* src = (const float*)d_in[1];
    const float* wq  = (const float*)d_in[2];
    const float* wk  = (const float*)d_in[3];
    const float* wv  = (const float*)d_in[4];
    const float* wm  = (const float*)d_in[5];
    const float* w1  = (const float*)d_in[6];
    const float* w2  = (const float*)d_in[7];
    const float* g1  = (const float*)d_in[8];
    const float* b1  = (const float*)d_in[9];
    const float* g2  = (const float*)d_in[10];
    const float* b2  = (const float*)d_in[11];
    float* out = (float*)d_out;

    cudaFuncSetAttribute(k1_mma, cudaFuncAttributeMaxDynamicSharedMemorySize, SMEM1M);
    cudaFuncSetAttribute(k2_mma, cudaFuncAttributeMaxDynamicSharedMemorySize, SMEM2M);
    cudaFuncSetAttribute(k3_mma, cudaFuncAttributeMaxDynamicSharedMemorySize, SMEM3M);

    k0_zero<<<512, 256>>>();
    k1_mma<<<dim3(SS/256, NHD), 256, SMEM1M>>>(src, wk, wv);
    k2_mma<<<dim3(LL/256, NHD), 256, SMEM2M>>>(x, wq);
    k3_mma<<<148, 256, SMEM3M>>>(x, wm, w1, w2, g1, b1, g2, b2, out);
}

// round 16
// speedup vs baseline: 1.5027x; 1.0487x over previous
#include <cuda_runtime.h>
#include <cuda_bf16.h>
#include <math.h>
#include <stdint.h>

#define NB 4
#define LL 4096
#define SS 4096
#define HH 8
#define NHD 32
#define NTOK (NB*LL*HH)    // 131072

typedef __nv_bfloat16 bf16;

// ---------------- scratch ----------------
__device__ float g_kv[NHD*64*64];
__device__ float g_ksum[NHD*64];
__device__ float g_msg[NTOK*64];

// ---------------- k0 ----------------
__global__ void k0_zero() {
    int i = blockIdx.x * blockDim.x + threadIdx.x;
    if (i < NHD*64*64) g_kv[i] = 0.f;
    if (i < NHD*64)    g_ksum[i] = 0.f;
}

// ================= mma helpers =================
__device__ __forceinline__ void mma_bf16(float d[4], const uint32_t a[4],
                                         uint32_t b0, uint32_t b1) {
    asm volatile("mma.sync.aligned.m16n8k16.row.col.f32.bf16.bf16.f32 "
        "{%0,%1,%2,%3}, {%4,%5,%6,%7}, {%8,%9}, {%0,%1,%2,%3};"
        : "+f"(d[0]), "+f"(d[1]), "+f"(d[2]), "+f"(d[3])
        : "r"(a[0]), "r"(a[1]), "r"(a[2]), "r"(a[3]), "r"(b0), "r"(b1));
}

__device__ __forceinline__ void split2(float v0, float v1, uint32_t& hi, uint32_t& lo) {
    bf16 h0 = __float2bfloat16(v0);
    bf16 h1 = __float2bfloat16(v1);
    __nv_bfloat162 hh = __halves2bfloat162(h0, h1);
    hi = *(uint32_t*)&hh;
    __nv_bfloat162 ll = __halves2bfloat162(
        __float2bfloat16(v0 - __bfloat162float(h0)),
        __float2bfloat16(v1 - __bfloat162float(h1)));
    lo = *(uint32_t*)&ll;
}

// warp GEMM: M32 (2 mtiles), N = NT*8, K = NK*16, 3-term bf16 split
template<int NT, int NK>
__device__ __forceinline__ void warp_gemm(float acc[2][NT][4],
    const bf16* __restrict__ Ah, const bf16* __restrict__ Al, int sa, int mrow0,
    const bf16* __restrict__ Bh, const bf16* __restrict__ Bl, int sb, int ncol0,
    int lane)
{
    int r = lane >> 2, c2 = (lane & 3)*2;
    #pragma unroll
    for (int ks = 0; ks < NK; ks++) {
        uint32_t ah[2][4], al[2][4];
        #pragma unroll
        for (int mt = 0; mt < 2; mt++) {
            const bf16* pa = Ah + (mrow0 + mt*16 + r)*sa + ks*16 + c2;
            const bf16* pl = Al + (mrow0 + mt*16 + r)*sa + ks*16 + c2;
            ah[mt][0] = *(const uint32_t*)(pa);
            ah[mt][1] = *(const uint32_t*)(pa + 8*sa);
            ah[mt][2] = *(const uint32_t*)(pa + 8);
            ah[mt][3] = *(const uint32_t*)(pa + 8*sa + 8);
            al[mt][0] = *(const uint32_t*)(pl);
            al[mt][1] = *(const uint32_t*)(pl + 8*sa);
            al[mt][2] = *(const uint32_t*)(pl + 8);
            al[mt][3] = *(const uint32_t*)(pl + 8*sa + 8);
        }
        #pragma unroll
        for (int nt = 0; nt < NT; nt++) {
            const bf16* pbh = Bh + (ncol0 + nt*8 + r)*sb + ks*16 + c2;
            const bf16* pbl = Bl + (ncol0 + nt*8 + r)*sb + ks*16 + c2;
            uint32_t bh0 = *(const uint32_t*)(pbh);
            uint32_t bh1 = *(const uint32_t*)(pbh + 8);
            uint32_t bl0 = *(const uint32_t*)(pbl);
            uint32_t bl1 = *(const uint32_t*)(pbl + 8);
            #pragma unroll
            for (int mt = 0; mt < 2; mt++) {
                mma_bf16(acc[mt][nt], ah[mt], bh0, bh1);
                mma_bf16(acc[mt][nt], ah[mt], bl0, bl1);
                mma_bf16(acc[mt][nt], al[mt], bh0, bh1);
            }
        }
    }
}

__device__ __forceinline__ float elu1(float v) {
    return (v > 0.f) ? (v + 1.f) : expf(v);
}

// =================================================================
// k1: kT/vT projection + kv outer product; 512 s per block (4 subs)
// grid (SS/512, NHD) = 256 blocks, block 256, smem 108.5KB -> 2 CTA/SM
// =================================================================
#define SO1_WKH 0
#define SO1_WKL 9216
#define SO1_WVH 18432
#define SO1_WVL 27648
#define SO1_SRH 36864
#define SO1_SRL 55296
#define SO1_KTH 73728
#define SO1_KTL 91136
#define SO1_VTH 36864          // alias over SRH
#define SO1_VTL 55296          // alias over SRL
#define SMEM1M  108544

__global__ void __launch_bounds__(256, 2)
k1_mma(const float* __restrict__ src,
       const float* __restrict__ wk,
       const float* __restrict__ wv) {
    extern __shared__ char smem[];
    bf16* WKH = (bf16*)(smem + SO1_WKH);
    bf16* WKL = (bf16*)(smem + SO1_WKL);
    bf16* WVH = (bf16*)(smem + SO1_WVH);
    bf16* WVL = (bf16*)(smem + SO1_WVL);
    bf16* SRH = (bf16*)(smem + SO1_SRH);   // src [s=128][d=64] stride 72
    bf16* SRL = (bf16*)(smem + SO1_SRL);
    bf16* KTH = (bf16*)(smem + SO1_KTH);   // kT [dk=64][s=128] stride 136
    bf16* KTL = (bf16*)(smem + SO1_KTL);
    bf16* VTH = (bf16*)(smem + SO1_VTH);   // vT aliases src
    bf16* VTL = (bf16*)(smem + SO1_VTL);

    int tid = threadIdx.x, lane = tid & 31, w = tid >> 5;
    int r = lane >> 2, c2 = (lane & 3)*2;
    int nh = blockIdx.y, n = nh >> 3, h = nh & 7;
    int wM = w & 1, wN = w >> 1;   // 2 x 4

    for (int i = tid; i < 4096; i += 256) {
        int e = i >> 6, d = i & 63;
        float vk = wk[i], vv = wv[i];
        bf16 hk = __float2bfloat16(vk);
        WKH[e*72 + d] = hk;
        WKL[e*72 + d] = __float2bfloat16(vk - __bfloat162float(hk));
        bf16 hv = __float2bfloat16(vv);
        WVH[e*72 + d] = hv;
        WVL[e*72 + d] = __float2bfloat16(vv - __bfloat162float(hv));
    }

    // outer-product accumulator + ksum, carried across subs (K grows to 512)
    int wK = w >> 2, wM2 = (w >> 1) & 1, wN2 = w & 1;
    float accO[2][4][4];
    #pragma unroll
    for (int i = 0; i < 2; i++)
        #pragma unroll
        for (int j = 0; j < 4; j++)
            #pragma unroll
            for (int q = 0; q < 4; q++) accO[i][j][q] = 0.f;
    float kreg = 0.f;

    for (int sub = 0; sub < 4; sub++) {
        int s0 = blockIdx.x*512 + sub*128;
        __syncthreads();   // prior KT/VT reads done (iter>0); weight stores visible (iter 0)

        for (int i = tid; i < 4096; i += 256) {
            int t = i >> 5, j = (i & 31)*2;
            float2 sv = *(const float2*)(src + ((size_t)(n*SS + s0 + t)*HH + h)*64 + j);
            uint32_t hi, lo;
            split2(sv.x, sv.y, hi, lo);
            *(uint32_t*)(SRH + t*72 + j) = hi;
            *(uint32_t*)(SRL + t*72 + j) = lo;
        }
        __syncthreads();

        // ---- proj K (flipped): kT[e][s] = wk @ src^T  (M=64, N=128, K=64) ----
        {
            float accK[2][4][4];
            #pragma unroll
            for (int i = 0; i < 2; i++)
                #pragma unroll
                for (int j = 0; j < 4; j++)
                    #pragma unroll
                    for (int q = 0; q < 4; q++) accK[i][j][q] = 0.f;
            warp_gemm<4,4>(accK, WKH, WKL, 72, wM*32, SRH, SRL, 72, wN*32, lane);
            #pragma unroll
            for (int mt = 0; mt < 2; mt++)
                #pragma unroll
                for (int nt = 0; nt < 4; nt++) {
                    int rr = wM*32 + mt*16 + r;
                    int cc = wN*32 + nt*8 + c2;
                    uint32_t hi, lo;
                    split2(elu1(accK[mt][nt][0]), elu1(accK[mt][nt][1]), hi, lo);
                    *(uint32_t*)(KTH + rr*136 + cc) = hi;
                    *(uint32_t*)(KTL + rr*136 + cc) = lo;
                    split2(elu1(accK[mt][nt][2]), elu1(accK[mt][nt][3]), hi, lo);
                    *(uint32_t*)(KTH + (rr+8)*136 + cc) = hi;
                    *(uint32_t*)(KTL + (rr+8)*136 + cc) = lo;
                }
        }

        // ---- proj V; acc held in regs across the sync ----
        {
            float accV[2][4][4];
            #pragma unroll
            for (int i = 0; i < 2; i++)
                #pragma unroll
                for (int j = 0; j < 4; j++)
                    #pragma unroll
                    for (int q = 0; q < 4; q++) accV[i][j][q] = 0.f;
            warp_gemm<4,4>(accV, WVH, WVL, 72, wM*32, SRH, SRL, 72, wN*32, lane);
            __syncthreads();   // all SR reads complete
            #pragma unroll
            for (int mt = 0; mt < 2; mt++)
                #pragma unroll
                for (int nt = 0; nt < 4; nt++) {
                    int rr = wM*32 + mt*16 + r;
                    int cc = wN*32 + nt*8 + c2;
                    uint32_t hi, lo;
                    split2(accV[mt][nt][0], accV[mt][nt][1], hi, lo);
                    *(uint32_t*)(VTH + rr*136 + cc) = hi;
                    *(uint32_t*)(VTL + rr*136 + cc) = lo;
                    split2(accV[mt][nt][2], accV[mt][nt][3], hi, lo);
                    *(uint32_t*)(VTH + (rr+8)*136 + cc) = hi;
                    *(uint32_t*)(VTL + (rr+8)*136 + cc) = lo;
                }
        }
        __syncthreads();

        // ---- outer: kv[dk][dv] += kT @ vT^T  (M=64, N=64, K=128 split x2) ----
        warp_gemm<4,4>(accO, KTH + wK*64, KTL + wK*64, 136, wM2*32,
                             VTH + wK*64, VTL + wK*64, 136, wN2*32, lane);

        // ---- ksum partial (4 threads per dk row) ----
        {
            int row = tid >> 2, q = tid & 3;
            const __nv_bfloat162* ph = (const __nv_bfloat162*)(KTH + row*136) + q*16;
            const __nv_bfloat162* pl = (const __nv_bfloat162*)(KTL + row*136) + q*16;
            float s = 0.f;
            #pragma unroll
            for (int i = 0; i < 16; i++) {
                float2 a = __bfloat1622float2(ph[i]);
                float2 b = __bfloat1622float2(pl[i]);
                s += a.x + a.y + b.x + b.y;
            }
            kreg += s;
        }
    }

    // ---- global accumulation (once per block) ----
    {
        float* kvg = g_kv + nh*4096;
        #pragma unroll
        for (int mt = 0; mt < 2; mt++)
            #pragma unroll
            for (int nt = 0; nt < 4; nt++) {
                int rr = wM2*32 + mt*16 + r;
                int cc = wN2*32 + nt*8 + c2;
                atomicAdd(kvg + rr*64 + cc,       accO[mt][nt][0]);
                atomicAdd(kvg + rr*64 + cc + 1,   accO[mt][nt][1]);
                atomicAdd(kvg + (rr+8)*64 + cc,   accO[mt][nt][2]);
                atomicAdd(kvg + (rr+8)*64 + cc+1, accO[mt][nt][3]);
            }
    }
    {
        int row = tid >> 2, q = tid & 3;
        kreg += __shfl_xor_sync(0xffffffffu, kreg, 1);
        kreg += __shfl_xor_sync(0xffffffffu, kreg, 2);
        if (q == 0) atomicAdd(g_ksum + nh*64 + row, kreg);
    }
}

// =================================================================
// k2: q projection + attention apply; 512 l per block (4 subs)
// grid (LL/512, NHD) = 256 blocks, block 256, smem ~74KB -> 2 CTA/SM
// =================================================================
#define SO2_WQH 0
#define SO2_WQL 9216
#define SO2_KVH 18432
#define SO2_KVL 27648
#define SO2_XH  36864
#define SO2_XL  55296
#define SO2_KS  73728
#define SO2_ZB  73984
#define SMEM2M  74496

__global__ void __launch_bounds__(256, 2)
k2_mma(const float* __restrict__ x,
       const float* __restrict__ wq) {
    extern __shared__ char smem[];
    bf16* WQH = (bf16*)(smem + SO2_WQH);
    bf16* WQL = (bf16*)(smem + SO2_WQL);
    bf16* KVH = (bf16*)(smem + SO2_KVH);
    bf16* KVL = (bf16*)(smem + SO2_KVL);
    bf16* XH  = (bf16*)(smem + SO2_XH);
    bf16* XL  = (bf16*)(smem + SO2_XL);
    float* ksb = (float*)(smem + SO2_KS);
    float* zb  = (float*)(smem + SO2_ZB);

    int tid = threadIdx.x, lane = tid & 31, w = tid >> 5;
    int r = lane >> 2, c2 = (lane & 3)*2;
    int wM = w & 3, wN = w >> 2;
    int nh = blockIdx.y, n = nh >> 3, h = nh & 7;

    for (int i = tid; i < 4096; i += 256) {
        int e = i >> 6, d = i & 63;
        float v = wq[i];
        bf16 hh = __float2bfloat16(v);
        WQH[e*72 + d] = hh;
        WQL[e*72 + d] = __float2bfloat16(v - __bfloat162float(hh));
        int dk = i >> 6, dv = i & 63;
        float kvv = g_kv[nh*4096 + i];
        bf16 kh = __float2bfloat16(kvv);
        KVH[dv*72 + dk] = kh;
        KVL[dv*72 + dk] = __float2bfloat16(kvv - __bfloat162float(kh));
    }
    if (tid < 64) ksb[tid] = g_ksum[nh*64 + tid];

    for (int sub = 0; sub < 4; sub++) {
        int l0 = blockIdx.x*512 + sub*128;
        __syncthreads();   // prior X reads done (iter>0); weight/kv visible (iter 0)

        for (int i = tid; i < 4096; i += 256) {
            int t = i >> 5, j = (i & 31)*2;
            float2 xv = *(const float2*)(x + ((size_t)(n*LL + l0 + t)*HH + h)*64 + j);
            uint32_t hi, lo;
            split2(xv.x, xv.y, hi, lo);
            *(uint32_t*)(XH + t*72 + j) = hi;
            *(uint32_t*)(XL + t*72 + j) = lo;
        }
        __syncthreads();

        float accQ[2][4][4];
        #pragma unroll
        for (int i = 0; i < 2; i++)
            #pragma unroll
            for (int j = 0; j < 4; j++)
                #pragma unroll
                for (int q = 0; q < 4; q++) accQ[i][j][q] = 0.f;
        warp_gemm<4,4>(accQ, XH, XL, 72, wM*32, WQH, WQL, 72, wN*32, lane);
        #pragma unroll
        for (int i = 0; i < 2; i++)
            #pragma unroll
            for (int j = 0; j < 4; j++)
                #pragma unroll
                for (int q = 0; q < 4; q++) accQ[i][j][q] = elu1(accQ[i][j][q]);
        __syncthreads();

        #pragma unroll
        for (int mt = 0; mt < 2; mt++)
            #pragma unroll
            for (int nt = 0; nt < 4; nt++) {
                int rr = wM*32 + mt*16 + r;
                int cc = wN*32 + nt*8 + c2;
                uint32_t hi, lo;
                split2(accQ[mt][nt][0], accQ[mt][nt][1], hi, lo);
                *(uint32_t*)(XH + rr*72 + cc) = hi;
                *(uint32_t*)(XL + rr*72 + cc) = lo;
                split2(accQ[mt][nt][2], accQ[mt][nt][3], hi, lo);
                *(uint32_t*)(XH + (rr+8)*72 + cc) = hi;
                *(uint32_t*)(XL + (rr+8)*72 + cc) = lo;
            }
        __syncthreads();

        if (tid < 128) {
            const __nv_bfloat162* ph = (const __nv_bfloat162*)(XH + tid*72);
            const __nv_bfloat162* pl = (const __nv_bfloat162*)(XL + tid*72);
            float s = 0.f;
            #pragma unroll 8
            for (int i = 0; i < 32; i++) {
                float2 a = __bfloat1622float2(ph[i]);
                float2 b = __bfloat1622float2(pl[i]);
                s += (a.x + b.x)*ksb[2*i] + (a.y + b.y)*ksb[2*i + 1];
            }
            zb[tid] = 1.f / (s + 1e-6f);
        }
        __syncthreads();

        float accM[2][4][4];
        #pragma unroll
        for (int i = 0; i < 2; i++)
            #pragma unroll
            for (int j = 0; j < 4; j++)
                #pragma unroll
                for (int q = 0; q < 4; q++) accM[i][j][q] = 0.f;
        warp_gemm<4,4>(accM, XH, XL, 72, wM*32, KVH, KVL, 72, wN*32, lane);
        #pragma unroll
        for (int mt = 0; mt < 2; mt++)
            #pragma unroll
            for (int nt = 0; nt < 4; nt++) {
                int rr = wM*32 + mt*16 + r;
                int cc = wN*32 + nt*8 + c2;
                float z0 = zb[rr], z1 = zb[rr + 8];
                size_t row0 = ((size_t)(n*LL + l0 + rr)*HH + h)*64;
                size_t row1 = ((size_t)(n*LL + l0 + rr + 8)*HH + h)*64;
                float2 o0 = {accM[mt][nt][0]*z0, accM[mt][nt][1]*z0};
                float2 o1 = {accM[mt][nt][2]*z1, accM[mt][nt][3]*z1};
                *(float2*)(g_msg + row0 + cc) = o0;
                *(float2*)(g_msg + row1 + cc) = o1;
            }
    }
}

// =================================================================
// k3: merge+LN1+FFN+LN2+residual — 256 threads; per-thread LN reduce
// =================================================================
__device__ __forceinline__ void quad_reduce2(float& s, float& q) {
    s += __shfl_xor_sync(0xffffffffu, s, 1);
    q += __shfl_xor_sync(0xffffffffu, q, 1);
    s += __shfl_xor_sync(0xffffffffu, s, 2);
    q += __shfl_xor_sync(0xffffffffu, q, 2);
}

__device__ __forceinline__ void ln_row(const float* ps, const float* pq, int rr,
                                       float& mean, float& inv) {
    float s = ps[rr*4] + ps[rr*4+1] + ps[rr*4+2] + ps[rr*4+3];
    float q = pq[rr*4] + pq[rr*4+1] + pq[rr*4+2] + pq[rr*4+3];
    mean = s * (1.f/64.f);
    float var = q * (1.f/64.f) - mean*mean;
    inv = rsqrtf(var + 1e-5f);
}

#define SO_W1H 0
#define SO_W1L 34816
#define SO_W2H 69632
#define SO_W2L 87040
#define SO_WMH 104448
#define SO_WML 113664
#define SO_HH  122880
#define SO_HL  140288
#define SO_H1H 157696
#define SO_H1L 175104
#define SO_XB  192512
#define SO_GB  209408
#define SO_PS  210432
#define SO_PQ  211456
#define SMEM3M 212480

__global__ void __launch_bounds__(256, 1)
k3_mma(const float* __restrict__ x,
       const float* __restrict__ wm,
       const float* __restrict__ w1,
       const float* __restrict__ w2,
       const float* __restrict__ g1, const float* __restrict__ b1,
       const float* __restrict__ g2, const float* __restrict__ b2,
       float* __restrict__ out) {
    extern __shared__ char smem[];
    bf16* W1H = (bf16*)(smem + SO_W1H);
    bf16* W1L = (bf16*)(smem + SO_W1L);
    bf16* W2H = (bf16*)(smem + SO_W2H);
    bf16* W2L = (bf16*)(smem + SO_W2L);
    bf16* WMH = (bf16*)(smem + SO_WMH);
    bf16* WML = (bf16*)(smem + SO_WML);
    bf16* Hh  = (bf16*)(smem + SO_HH);
    bf16* Hl  = (bf16*)(smem + SO_HL);
    bf16* H1h = (bf16*)(smem + SO_H1H);
    bf16* H1l = (bf16*)(smem + SO_H1L);
    float* xb    = (float*)(smem + SO_XB);
    float* gbuf  = (float*)(smem + SO_GB);
    float* ps    = (float*)(smem + SO_PS);
    float* pq    = (float*)(smem + SO_PQ);

    int tid = threadIdx.x, lane = tid & 31, w = tid >> 5;
    int wM = w & 1, wN = w >> 1;
    int r = lane >> 2, c2 = (lane & 3)*2;

    for (int i = tid; i < 16384; i += 256) {
        int nn = i >> 7, kk = i & 127;
        float v = w1[i];
        bf16 h = __float2bfloat16(v);
        W1H[nn*136 + kk] = h;
        W1L[nn*136 + kk] = __float2bfloat16(v - __bfloat162float(h));
    }
    for (int i = tid; i < 8192; i += 256) {
        int nn = i >> 7, kk = i & 127;
        float v = w2[i];
        bf16 h = __float2bfloat16(v);
        W2H[nn*136 + kk] = h;
        W2L[nn*136 + kk] = __float2bfloat16(v - __bfloat162float(h));
    }
    for (int i = tid; i < 4096; i += 256) {
        int nn = i >> 6, kk = i & 63;
        float v = wm[i];
        bf16 h = __float2bfloat16(v);
        WMH[nn*72 + kk] = h;
        WML[nn*72 + kk] = __float2bfloat16(v - __bfloat162float(h));
    }
    if (tid < 64) {
        gbuf[tid]       = g1[tid];
        gbuf[64 + tid]  = b1[tid];
        gbuf[128 + tid] = g2[tid];
        gbuf[192 + tid] = b2[tid];
    }
    __syncthreads();

    for (int tile = blockIdx.x; tile < NTOK/64; tile += gridDim.x) {
        int tok0 = tile * 64;

        for (int i = tid; i < 2048; i += 256) {
            int t = i >> 5, j = (i & 31)*2;
            float2 mv = *(const float2*)(g_msg + (size_t)(tok0 + t)*64 + j);
            uint32_t hi, lo;
            split2(mv.x, mv.y, hi, lo);
            *(uint32_t*)(H1h + t*136 + j) = hi;
            *(uint32_t*)(H1l + t*136 + j) = lo;
            float2 xv = *(const float2*)(x + (size_t)(tok0 + t)*64 + j);
            split2(xv.x, xv.y, hi, lo);
            *(uint32_t*)(Hh + t*136 + j) = hi;
            *(uint32_t*)(Hl + t*136 + j) = lo;
            *(float2*)(xb + t*66 + j) = xv;
        }
        __syncthreads();

        // ---- Stage A: msg @ wm^T ----
        float accA[2][2][4];
        #pragma unroll
        for (int i = 0; i < 2; i++)
            #pragma unroll
            for (int j = 0; j < 2; j++)
                #pragma unroll
                for (int q = 0; q < 4; q++) accA[i][j][q] = 0.f;
        warp_gemm<2,4>(accA, H1h, H1l, 136, wM*32, WMH, WML, 72, wN*16, lane);

        // LN1 partial stats
        #pragma unroll
        for (int mt = 0; mt < 2; mt++) {
            float s0 = 0.f, q0 = 0.f, s1 = 0.f, q1 = 0.f;
            #pragma unroll
            for (int nt = 0; nt < 2; nt++) {
                float a0 = accA[mt][nt][0], a1 = accA[mt][nt][1];
                float a2 = accA[mt][nt][2], a3 = accA[mt][nt][3];
                s0 += a0 + a1; q0 += a0*a0 + a1*a1;
                s1 += a2 + a3; q1 += a2*a2 + a3*a3;
            }
            quad_reduce2(s0, q0);
            quad_reduce2(s1, q1);
            if ((lane & 3) == 0) {
                int rr = wM*32 + mt*16 + r;
                ps[rr*4 + wN] = s0;      pq[rr*4 + wN] = q0;
                ps[(rr+8)*4 + wN] = s1;  pq[(rr+8)*4 + wN] = q1;
            }
        }
        __syncthreads();

        // LN1 apply (per-thread final reduce from ps/pq)
        #pragma unroll
        for (int mt = 0; mt < 2; mt++) {
            int rr = wM*32 + mt*16 + r;
            float m0, i0, m1, i1;
            ln_row(ps, pq, rr, m0, i0);
            ln_row(ps, pq, rr + 8, m1, i1);
            #pragma unroll
            for (int nt = 0; nt < 2; nt++) {
                int cc = wN*16 + nt*8 + c2;
                float y0 = (accA[mt][nt][0] - m0)*i0*gbuf[cc]   + gbuf[64+cc];
                float y1 = (accA[mt][nt][1] - m0)*i0*gbuf[cc+1] + gbuf[64+cc+1];
                uint32_t hi, lo;
                split2(y0, y1, hi, lo);
                *(uint32_t*)(Hh + rr*136 + 64 + cc) = hi;
                *(uint32_t*)(Hl + rr*136 + 64 + cc) = lo;
                float y2 = (accA[mt][nt][2] - m1)*i1*gbuf[cc]   + gbuf[64+cc];
                float y3 = (accA[mt][nt][3] - m1)*i1*gbuf[cc+1] + gbuf[64+cc+1];
                split2(y2, y3, hi, lo);
                *(uint32_t*)(Hh + (rr+8)*136 + 64 + cc) = hi;
                *(uint32_t*)(Hl + (rr+8)*136 + 64 + cc) = lo;
            }
        }
        __syncthreads();

        // ---- Stage B: [x;m] @ w1^T ----
        float accB[2][4][4];
        #pragma unroll
        for (int i = 0; i < 2; i++)
            #pragma unroll
            for (int j = 0; j < 4; j++)
                #pragma unroll
                for (int q = 0; q < 4; q++) accB[i][j][q] = 0.f;
        warp_gemm<4,8>(accB, Hh, Hl, 136, wM*32, W1H, W1L, 136, wN*32, lane);

        #pragma unroll
        for (int mt = 0; mt < 2; mt++)
            #pragma unroll
            for (int nt = 0; nt < 4; nt++) {
                int rr = wM*32 + mt*16 + r;
                int cc = wN*32 + nt*8 + c2;
                uint32_t hi, lo;
                split2(fmaxf(accB[mt][nt][0], 0.f), fmaxf(accB[mt][nt][1], 0.f), hi, lo);
                *(uint32_t*)(H1h + rr*136 + cc) = hi;
                *(uint32_t*)(H1l + rr*136 + cc) = lo;
                split2(fmaxf(accB[mt][nt][2], 0.f), fmaxf(accB[mt][nt][3], 0.f), hi, lo);
                *(uint32_t*)(H1h + (rr+8)*136 + cc) = hi;
                *(uint32_t*)(H1l + (rr+8)*136 + cc) = lo;
            }
        __syncthreads();

        // ---- Stage C: h1 @ w2^T ----
        float accC[2][2][4];
        #pragma unroll
        for (int i = 0; i < 2; i++)
            #pragma unroll
            for (int j = 0; j < 2; j++)
                #pragma unroll
                for (int q = 0; q < 4; q++) accC[i][j][q] = 0.f;
        warp_gemm<2,8>(accC, H1h, H1l, 136, wM*32, W2H, W2L, 136, wN*16, lane);

        // LN2 partial stats
        #pragma unroll
        for (int mt = 0; mt < 2; mt++) {
            float s0 = 0.f, q0 = 0.f, s1 = 0.f, q1 = 0.f;
            #pragma unroll
            for (int nt = 0; nt < 2; nt++) {
                float a0 = accC[mt][nt][0], a1 = accC[mt][nt][1];
                float a2 = accC[mt][nt][2], a3 = accC[mt][nt][3];
                s0 += a0 + a1; q0 += a0*a0 + a1*a1;
                s1 += a2 + a3; q1 += a2*a2 + a3*a3;
            }
            quad_reduce2(s0, q0);
            quad_reduce2(s1, q1);
            if ((lane & 3) == 0) {
                int rr = wM*32 + mt*16 + r;
                ps[rr*4 + wN] = s0;      pq[rr*4 + wN] = q0;
                ps[(rr+8)*4 + wN] = s1;  pq[(rr+8)*4 + wN] = q1;
            }
        }
        __syncthreads();

        // LN2 + residual -> gmem (per-thread final reduce)
        #pragma unroll
        for (int mt = 0; mt < 2; mt++) {
            int rr = wM*32 + mt*16 + r;
            float m0, i0, m1, i1;
            ln_row(ps, pq, rr, m0, i0);
            ln_row(ps, pq, rr + 8, m1, i1);
            #pragma unroll
            for (int nt = 0; nt < 2; nt++) {
                int cc = wN*16 + nt*8 + c2;
                float2 xv = *(const float2*)(xb + rr*66 + cc);
                float2 o0;
                o0.x = xv.x + (accC[mt][nt][0] - m0)*i0*gbuf[128+cc]   + gbuf[192+cc];
                o0.y = xv.y + (accC[mt][nt][1] - m0)*i0*gbuf[128+cc+1] + gbuf[192+cc+1];
                *(float2*)(out + (size_t)(tok0 + rr)*64 + cc) = o0;
                float2 xw = *(const float2*)(xb + (rr+8)*66 + cc);
                float2 o1;
                o1.x = xw.x + (accC[mt][nt][2] - m1)*i1*gbuf[128+cc]   + gbuf[192+cc];
                o1.y = xw.y + (accC[mt][nt][3] - m1)*i1*gbuf[128+cc+1] + gbuf[192+cc+1];
                *(float2*)(out + (size_t)(tok0 + rr + 8)*64 + cc) = o1;
            }
        }
        __syncthreads();
    }
}

// ---------------- launch ----------------
extern "C" void kernel_launch(void* const* d_in, const int* in_sizes, int n_in,
                              void* d_out, int out_size) {
    const float* x   = (const float*)d_in[0];
    const float* src = (const float*)d_in[1];
    const float* wq  = (const float*)d_in[2];
    const float* wk  = (const float*)d_in[3];
    const float* wv  = (const float*)d_in[4];
    const float* wm  = (const float*)d_in[5];
    const float* w1  = (const float*)d_in[6];
    const float* w2  = (const float*)d_in[7];
    const float* g1  = (const float*)d_in[8];
    const float* b1  = (const float*)d_in[9];
    const float* g2  = (const float*)d_in[10];
    const float* b2  = (const float*)d_in[11];
    float* out = (float*)d_out;

    cudaFuncSetAttribute(k1_mma, cudaFuncAttributeMaxDynamicSharedMemorySize, SMEM1M);
    cudaFuncSetAttribute(k2_mma, cudaFuncAttributeMaxDynamicSharedMemorySize, SMEM2M);
    cudaFuncSetAttribute(k3_mma, cudaFuncAttributeMaxDynamicSharedMemorySize, SMEM3M);

    k0_zero<<<512, 256>>>();
    k1_mma<<<dim3(SS/512, NHD), 256, SMEM1M>>>(src, wk, wv);
    k2_mma<<<dim3(LL/512, NHD), 256, SMEM2M>>>(x, wq);
    k3_mma<<<148, 256, SMEM3M>>>(x, wm, w1, w2, g1, b1, g2, b2, out);
}